// round 1
// baseline (speedup 1.0000x reference)
#include <cuda_runtime.h>

#define N 8192
#define C 512

// ---------------- scratch (device globals; no allocation allowed) ----------------
__device__ float g_Vn[N * C];
__device__ float g_Tn[N * C];
__device__ float g_PVn[N * C];
__device__ float g_PTn[N * C];
__device__ float g_diag1[N];   // v_n[i] . p_t_n[i]  (diag of s1, also loss term 2)
__device__ float g_diag2[N];   // t_n[i] . p_v_n[i]  (diag of s2, also loss term 1)
__device__ int   g_cnt1[N];    // #{j != i : s1[i,j] > s1[i,i]}
__device__ int   g_cnt2[N];
__device__ float g_colsum[4][64][C];
__device__ float g_colsq[4][64][C];

// ---------------- kernel 0: zero the count accumulators (graph replays!) --------
__global__ void zero_cnt_kernel() {
    int i = blockIdx.x * blockDim.x + threadIdx.x;
    if (i < N) { g_cnt1[i] = 0; g_cnt2[i] = 0; }
}

__device__ __forceinline__ float dot4(float4 a, float4 b) {
    return a.x * b.x + a.y * b.y + a.z * b.z + a.w * b.w;
}

// ---------------- kernel 1: per-row normalize + row-local dots ------------------
// One block per row, 128 threads; each thread owns one float4 per matrix.
__global__ void normalize_kernel(const float* __restrict__ V, const float* __restrict__ T,
                                 const float* __restrict__ PV, const float* __restrict__ PT) {
    int row = blockIdx.x;
    int t   = threadIdx.x;
    size_t base = (size_t)row * C + 4 * t;

    float4 v  = *(const float4*)(V  + base);
    float4 tf = *(const float4*)(T  + base);
    float4 pv = *(const float4*)(PV + base);
    float4 pt = *(const float4*)(PT + base);

    float p0 = dot4(v, v);
    float p1 = dot4(tf, tf);
    float p2 = dot4(pv, pv);
    float p3 = dot4(pt, pt);
    float p4 = dot4(v, pt);   // raw v . p_t
    float p5 = dot4(tf, pv);  // raw t . p_v

#pragma unroll
    for (int m = 16; m; m >>= 1) {
        p0 += __shfl_xor_sync(0xffffffffu, p0, m);
        p1 += __shfl_xor_sync(0xffffffffu, p1, m);
        p2 += __shfl_xor_sync(0xffffffffu, p2, m);
        p3 += __shfl_xor_sync(0xffffffffu, p3, m);
        p4 += __shfl_xor_sync(0xffffffffu, p4, m);
        p5 += __shfl_xor_sync(0xffffffffu, p5, m);
    }
    __shared__ float sm[4][6];
    int w = t >> 5;
    if ((t & 31) == 0) {
        sm[w][0] = p0; sm[w][1] = p1; sm[w][2] = p2;
        sm[w][3] = p3; sm[w][4] = p4; sm[w][5] = p5;
    }
    __syncthreads();
    float s0 = sm[0][0] + sm[1][0] + sm[2][0] + sm[3][0];
    float s1 = sm[0][1] + sm[1][1] + sm[2][1] + sm[3][1];
    float s2 = sm[0][2] + sm[1][2] + sm[2][2] + sm[3][2];
    float s3 = sm[0][3] + sm[1][3] + sm[2][3] + sm[3][3];
    float s4 = sm[0][4] + sm[1][4] + sm[2][4] + sm[3][4];
    float s5 = sm[0][5] + sm[1][5] + sm[2][5] + sm[3][5];

    float rv  = rsqrtf(s0);
    float rt_ = rsqrtf(s1);
    float rpv = rsqrtf(s2);
    float rpt = rsqrtf(s3);

    *(float4*)(g_Vn  + base) = make_float4(v.x * rv,  v.y * rv,  v.z * rv,  v.w * rv);
    *(float4*)(g_Tn  + base) = make_float4(tf.x * rt_, tf.y * rt_, tf.z * rt_, tf.w * rt_);
    *(float4*)(g_PVn + base) = make_float4(pv.x * rpv, pv.y * rpv, pv.z * rpv, pv.w * rpv);
    *(float4*)(g_PTn + base) = make_float4(pt.x * rpt, pt.y * rpt, pt.z * rpt, pt.w * rpt);

    if (t == 0) {
        g_diag1[row] = s4 * rv  * rpt;  // v_n . p_t_n
        g_diag2[row] = s5 * rt_ * rpv;  // t_n . p_v_n
    }
}

// ---------------- kernel 2: per-column partial sums for std ----------------------
// grid (64 row-chunks, 4 matrices), 512 threads = 512 columns (coalesced rows).
__global__ void colstats_kernel() {
    int mat = blockIdx.y, chunk = blockIdx.x, col = threadIdx.x;
    const float* M = (mat == 0) ? g_Vn : (mat == 1) ? g_Tn : (mat == 2) ? g_PVn : g_PTn;
    float s = 0.f, q = 0.f;
    int r0 = chunk * 128;
#pragma unroll 4
    for (int r = r0; r < r0 + 128; r++) {
        float x = M[(size_t)r * C + col];
        s += x;
        q += x * x;
    }
    g_colsum[mat][chunk][col] = s;
    g_colsq[mat][chunk][col]  = q;
}

// ---------------- kernel 3: fused SGEMM + rank-count epilogue --------------------
// C[i,j] = A[i,:] . B[j,:]  (both row-major, K-contiguous).
// 128x128 tile, BK=16, 256 threads, 8x8 per thread.
#define BM 128
#define BN 128
#define BK 16

__global__ __launch_bounds__(256, 2) void gemm_count_kernel() {
    const float* __restrict__ A  = (blockIdx.z == 0) ? g_Vn  : g_Tn;
    const float* __restrict__ B  = (blockIdx.z == 0) ? g_PTn : g_PVn;
    const float* __restrict__ Dg = (blockIdx.z == 0) ? g_diag1 : g_diag2;
    int* cnt = (blockIdx.z == 0) ? g_cnt1 : g_cnt2;

    __shared__ float As[BK][BM + 4];
    __shared__ float Bs[BK][BN + 4];

    int t  = threadIdx.x;
    int tx = t & 15;
    int ty = t >> 4;
    int rowBase = blockIdx.y * BM;
    int colBase = blockIdx.x * BN;

    float acc[8][8];
#pragma unroll
    for (int i = 0; i < 8; i++)
#pragma unroll
        for (int j = 0; j < 8; j++) acc[i][j] = 0.f;

    for (int kb = 0; kb < C; kb += BK) {
#pragma unroll
        for (int i = 0; i < 2; i++) {
            int f = t + i * 256;           // 0..511 float4 slots
            int r = f >> 2, seg = f & 3;   // row in tile, 4-float segment of BK
            float4 va = *(const float4*)&A[(size_t)(rowBase + r) * C + kb + seg * 4];
            As[seg * 4 + 0][r] = va.x;
            As[seg * 4 + 1][r] = va.y;
            As[seg * 4 + 2][r] = va.z;
            As[seg * 4 + 3][r] = va.w;
            float4 vb = *(const float4*)&B[(size_t)(colBase + r) * C + kb + seg * 4];
            Bs[seg * 4 + 0][r] = vb.x;
            Bs[seg * 4 + 1][r] = vb.y;
            Bs[seg * 4 + 2][r] = vb.z;
            Bs[seg * 4 + 3][r] = vb.w;
        }
        __syncthreads();
#pragma unroll
        for (int k = 0; k < BK; k++) {
            float a[8], b[8];
            *(float4*)(a)     = *(const float4*)&As[k][ty * 8];
            *(float4*)(a + 4) = *(const float4*)&As[k][ty * 8 + 4];
            *(float4*)(b)     = *(const float4*)&Bs[k][tx * 8];
            *(float4*)(b + 4) = *(const float4*)&Bs[k][tx * 8 + 4];
#pragma unroll
            for (int i = 0; i < 8; i++)
#pragma unroll
                for (int j = 0; j < 8; j++) acc[i][j] += a[i] * b[j];
        }
        __syncthreads();
    }

    // Epilogue: count entries strictly greater than the diagonal, skipping j == i.
#pragma unroll
    for (int i = 0; i < 8; i++) {
        int r = rowBase + ty * 8 + i;
        float d = __ldg(&Dg[r]);
        int c = 0;
#pragma unroll
        for (int j = 0; j < 8; j++) {
            int col = colBase + tx * 8 + j;
            c += (acc[i][j] > d && col != r) ? 1 : 0;
        }
        // reduce across the 16 tx-lanes (xor within the 16-lane half-warp)
        c += __shfl_xor_sync(0xffffffffu, c, 1);
        c += __shfl_xor_sync(0xffffffffu, c, 2);
        c += __shfl_xor_sync(0xffffffffu, c, 4);
        c += __shfl_xor_sync(0xffffffffu, c, 8);
        if (tx == 0) atomicAdd(&cnt[r], c);
    }
}

// ---------------- kernel 4: deterministic finalize -------------------------------
__global__ void finalize_kernel(float* __restrict__ out) {
    __shared__ float sm[16];
    int t = threadIdx.x;

    auto bsum = [&](float v) -> float {
#pragma unroll
        for (int m = 16; m; m >>= 1) v += __shfl_xor_sync(0xffffffffu, v, m);
        if ((t & 31) == 0) sm[t >> 5] = v;
        __syncthreads();
        float r = 0.f;
        if (t < 32) {
            r = (t < 16) ? sm[t] : 0.f;
#pragma unroll
            for (int m = 8; m; m >>= 1) r += __shfl_xor_sync(0xffffffffu, r, m);
        }
        __syncthreads();
        return r;  // valid in warp 0
    };

    // loss = -0.5*mean(diag2) - 0.5*mean(diag1)
    float s = 0.f;
    for (int i = t; i < N; i += 512) s += g_diag1[i] + g_diag2[i];
    float tot = bsum(s);
    if (t == 0) out[0] = -0.5f * tot / (float)N;

    // stats: mean over columns of std(ddof=1) over rows
    for (int m = 0; m < 4; m++) {
        float S = 0.f, Q = 0.f;
#pragma unroll 8
        for (int ch = 0; ch < 64; ch++) {
            S += g_colsum[m][ch][t];
            Q += g_colsq[m][ch][t];
        }
        float var = (Q - S * S / (float)N) / (float)(N - 1);
        float sd = sqrtf(fmaxf(var, 0.f));
        float tots = bsum(sd);
        if (t == 0) out[1 + m] = tots / (float)C;
    }

    // retrieval metrics
    for (int z = 0; z < 2; z++) {
        const int* cnt = z ? g_cnt2 : g_cnt1;
        float c1 = 0.f, c5 = 0.f, c10 = 0.f, cm = 0.f;
        for (int i = t; i < N; i += 512) {
            int p = cnt[i];
            c1  += (p < 1)  ? 1.f : 0.f;
            c5  += (p < 5)  ? 1.f : 0.f;
            c10 += (p < 10) ? 1.f : 0.f;
            cm  += (float)p;
        }
        float t1 = bsum(c1);
        float t5 = bsum(c5);
        float t10 = bsum(c10);
        float tm = bsum(cm);
        if (t == 0) {
            out[5 + 4 * z + 0] = t1 / (float)N;
            out[5 + 4 * z + 1] = t5 / (float)N;
            out[5 + 4 * z + 2] = t10 / (float)N;
            out[5 + 4 * z + 3] = tm / (float)N;
        }
    }
}

// ---------------- launch ---------------------------------------------------------
extern "C" void kernel_launch(void* const* d_in, const int* in_sizes, int n_in,
                              void* d_out, int out_size) {
    const float* V  = (const float*)d_in[0];
    const float* T  = (const float*)d_in[1];
    const float* PV = (const float*)d_in[2];
    const float* PT = (const float*)d_in[3];

    zero_cnt_kernel<<<16, 512>>>();
    normalize_kernel<<<N, 128>>>(V, T, PV, PT);
    colstats_kernel<<<dim3(64, 4), 512>>>();
    gemm_count_kernel<<<dim3(64, 64, 2), 256>>>();
    finalize_kernel<<<1, 512>>>((float*)d_out);
}

// round 4
// speedup vs baseline: 2.1346x; 2.1346x over previous
#include <cuda_runtime.h>
#include <cuda_bf16.h>
#include <cstdint>

#define N 8192
#define C 512

// ---------------- scratch (device globals; no allocation allowed) ----------------
// Problem z=0: A=Vn, B=PTn (s1).  z=1: A=Tn, B=PVn (s2).
__device__ __nv_bfloat16 g_Ahi[2][N * C];
__device__ __nv_bfloat16 g_Alo[2][N * C];
__device__ __nv_bfloat16 g_Bhi[2][N * C];
__device__ __nv_bfloat16 g_Blo[2][N * C];
__device__ float g_diag[2][N];   // exact fp32 diagonals
__device__ int   g_cnt[2][N];
__device__ float g_colsum[4][64][C];
__device__ float g_colsq[4][64][C];

__device__ __forceinline__ uint32_t smem_u32(const void* p) {
    uint32_t a;
    asm("{ .reg .u64 t; cvta.to.shared.u64 t, %1; cvt.u32.u64 %0, t; }" : "=r"(a) : "l"(p));
    return a;
}

// ---------------- kernel 0: zero count accumulators (graph replays!) ------------
__global__ void zero_cnt_kernel() {
    int i = blockIdx.x * blockDim.x + threadIdx.x;
    if (i < N) { g_cnt[0][i] = 0; g_cnt[1][i] = 0; }
}

__device__ __forceinline__ float dot4(float4 a, float4 b) {
    return a.x * b.x + a.y * b.y + a.z * b.z + a.w * b.w;
}

__device__ __forceinline__ void split_store(__nv_bfloat16* hi, __nv_bfloat16* lo, size_t base,
                                            float4 y, float r) {
    float x0 = y.x * r, x1 = y.y * r, x2 = y.z * r, x3 = y.w * r;
    __nv_bfloat16 h0 = __float2bfloat16(x0), h1 = __float2bfloat16(x1);
    __nv_bfloat16 h2 = __float2bfloat16(x2), h3 = __float2bfloat16(x3);
    __nv_bfloat16 l0 = __float2bfloat16(x0 - __bfloat162float(h0));
    __nv_bfloat16 l1 = __float2bfloat16(x1 - __bfloat162float(h1));
    __nv_bfloat16 l2 = __float2bfloat16(x2 - __bfloat162float(h2));
    __nv_bfloat16 l3 = __float2bfloat16(x3 - __bfloat162float(h3));
    __nv_bfloat162 a, b;
    a.x = h0; a.y = h1; b.x = h2; b.y = h3;
    *(__nv_bfloat162*)(hi + base) = a;
    *(__nv_bfloat162*)(hi + base + 2) = b;
    a.x = l0; a.y = l1; b.x = l2; b.y = l3;
    *(__nv_bfloat162*)(lo + base) = a;
    *(__nv_bfloat162*)(lo + base + 2) = b;
}

// ---------------- kernel 1: normalize + split to bf16 hi/lo + exact diagonals ---
__global__ void normalize_kernel(const float* __restrict__ V, const float* __restrict__ T,
                                 const float* __restrict__ PV, const float* __restrict__ PT) {
    int row = blockIdx.x;
    int t   = threadIdx.x;
    size_t base = (size_t)row * C + 4 * t;

    float4 v  = *(const float4*)(V  + base);
    float4 tf = *(const float4*)(T  + base);
    float4 pv = *(const float4*)(PV + base);
    float4 pt = *(const float4*)(PT + base);

    float p0 = dot4(v, v),  p1 = dot4(tf, tf), p2 = dot4(pv, pv);
    float p3 = dot4(pt, pt), p4 = dot4(v, pt), p5 = dot4(tf, pv);

#pragma unroll
    for (int m = 16; m; m >>= 1) {
        p0 += __shfl_xor_sync(0xffffffffu, p0, m);
        p1 += __shfl_xor_sync(0xffffffffu, p1, m);
        p2 += __shfl_xor_sync(0xffffffffu, p2, m);
        p3 += __shfl_xor_sync(0xffffffffu, p3, m);
        p4 += __shfl_xor_sync(0xffffffffu, p4, m);
        p5 += __shfl_xor_sync(0xffffffffu, p5, m);
    }
    __shared__ float sm[4][6];
    int w = t >> 5;
    if ((t & 31) == 0) {
        sm[w][0] = p0; sm[w][1] = p1; sm[w][2] = p2;
        sm[w][3] = p3; sm[w][4] = p4; sm[w][5] = p5;
    }
    __syncthreads();
    float s0 = sm[0][0] + sm[1][0] + sm[2][0] + sm[3][0];
    float s1 = sm[0][1] + sm[1][1] + sm[2][1] + sm[3][1];
    float s2 = sm[0][2] + sm[1][2] + sm[2][2] + sm[3][2];
    float s3 = sm[0][3] + sm[1][3] + sm[2][3] + sm[3][3];
    float s4 = sm[0][4] + sm[1][4] + sm[2][4] + sm[3][4];
    float s5 = sm[0][5] + sm[1][5] + sm[2][5] + sm[3][5];

    float rv  = rsqrtf(s0);
    float rt_ = rsqrtf(s1);
    float rpv = rsqrtf(s2);
    float rpt = rsqrtf(s3);

    split_store(g_Ahi[0], g_Alo[0], base, v,  rv);   // Vn  (A of problem 0)
    split_store(g_Ahi[1], g_Alo[1], base, tf, rt_);  // Tn  (A of problem 1)
    split_store(g_Bhi[1], g_Blo[1], base, pv, rpv);  // PVn (B of problem 1)
    split_store(g_Bhi[0], g_Blo[0], base, pt, rpt);  // PTn (B of problem 0)

    if (t == 0) {
        g_diag[0][row] = s4 * rv  * rpt;  // v_n . p_t_n
        g_diag[1][row] = s5 * rt_ * rpv;  // t_n . p_v_n
    }
}

// ---------------- kernel 2: per-column partial sums for std (from hi+lo) --------
__global__ void colstats_kernel() {
    int mat = blockIdx.y, chunk = blockIdx.x, col = threadIdx.x;
    const __nv_bfloat16* hi;
    const __nv_bfloat16* lo;
    switch (mat) {
        case 0: hi = g_Ahi[0]; lo = g_Alo[0]; break;  // v_feat
        case 1: hi = g_Ahi[1]; lo = g_Alo[1]; break;  // t_feat
        case 2: hi = g_Bhi[1]; lo = g_Blo[1]; break;  // p_v
        default: hi = g_Bhi[0]; lo = g_Blo[0]; break; // p_t
    }
    float s = 0.f, q = 0.f;
    int r0 = chunk * 128;
#pragma unroll 4
    for (int r = r0; r < r0 + 128; r++) {
        size_t idx = (size_t)r * C + col;
        float x = __bfloat162float(hi[idx]) + __bfloat162float(lo[idx]);
        s += x;
        q += x * x;
    }
    g_colsum[mat][chunk][col] = s;
    g_colsq[mat][chunk][col]  = q;
}

// ---------------- kernel 3: warp-MMA bf16 GEMM + fused rank-count epilogue ------
// C[i,j] = A[i,:].B[j,:], 3 hi/lo split segments, fp32 accumulation in registers.
// Tile 128x128, BK=64 (128B rows, SW128 swizzle), 3-stage cp.async pipeline.
#define TM 128
#define TN 128
#define TK 64
#define STAGES 3
#define STAGE_A (TM * 128)
#define STAGE_B (TN * 128)
#define STAGE_BYTES (STAGE_A + STAGE_B)   // 32768
#define SMEM_SIZE (STAGES * STAGE_BYTES)  // 98304
#define NCH 24                            // 3 segments * 8 k-chunks

__device__ __forceinline__ void ldsm4(uint32_t* r, uint32_t addr) {
    asm volatile("ldmatrix.sync.aligned.m8n8.x4.shared.b16 {%0,%1,%2,%3}, [%4];"
                 : "=r"(r[0]), "=r"(r[1]), "=r"(r[2]), "=r"(r[3]) : "r"(addr));
}
__device__ __forceinline__ void mma16816(float* d, const uint32_t* a, uint32_t b0, uint32_t b1) {
    asm volatile(
        "mma.sync.aligned.m16n8k16.row.col.f32.bf16.bf16.f32 "
        "{%0,%1,%2,%3}, {%4,%5,%6,%7}, {%8,%9}, {%0,%1,%2,%3};"
        : "+f"(d[0]), "+f"(d[1]), "+f"(d[2]), "+f"(d[3])
        : "r"(a[0]), "r"(a[1]), "r"(a[2]), "r"(a[3]), "r"(b0), "r"(b1));
}

__device__ __forceinline__ void load_tile(uint32_t smem_dst, const __nv_bfloat16* __restrict__ src,
                                          int row0, int kk, int tid) {
#pragma unroll
    for (int i = 0; i < 4; i++) {
        int idx = tid + i * 256;
        int r  = idx >> 3;
        int cb = (idx & 7) << 4;
        uint32_t dst = smem_dst + r * 128 + (cb ^ ((r & 7) << 4));
        const void* s = (const char*)(src + (size_t)(row0 + r) * C + kk) + cb;
        asm volatile("cp.async.cg.shared.global [%0], [%1], 16;" :: "r"(dst), "l"(s));
    }
}

__global__ void __launch_bounds__(256, 1) gemm_mma_kernel() {
    extern __shared__ char smem[];
    uint32_t sb = smem_u32(smem);
    int tid = threadIdx.x, lane = tid & 31, wid = tid >> 5;
    int z = blockIdx.z;
    int row0 = blockIdx.y * TM;
    int col0 = blockIdx.x * TN;

    const __nv_bfloat16* Ahi = g_Ahi[z];
    const __nv_bfloat16* Alo = g_Alo[z];
    const __nv_bfloat16* Bhi = g_Bhi[z];
    const __nv_bfloat16* Blo = g_Blo[z];

    auto load_chunk = [&](int ch, int stage) {
        int seg = ch >> 3;
        int kk  = (ch & 7) * TK;
        const __nv_bfloat16* As = (seg < 2)  ? Ahi : Alo;
        const __nv_bfloat16* Bs = (seg == 1) ? Blo : Bhi;
        uint32_t s = sb + stage * STAGE_BYTES;
        load_tile(s, As, row0, kk, tid);
        load_tile(s + STAGE_A, Bs, col0, kk, tid);
    };

    int wm = (wid >> 1) * 32;   // warp M offset (4 rows of warps)
    int wn = (wid & 1) * 64;    // warp N offset (2 cols of warps)

    float acc[2][8][4];
#pragma unroll
    for (int a = 0; a < 2; a++)
#pragma unroll
        for (int j = 0; j < 8; j++)
#pragma unroll
            for (int q = 0; q < 4; q++) acc[a][j][q] = 0.f;

    // prologue: stages 0 and 1
    load_chunk(0, 0);
    asm volatile("cp.async.commit_group;");
    load_chunk(1, 1);
    asm volatile("cp.async.commit_group;");

    // ldmatrix address components (loop-invariant)
    int arow = wm + (lane & 15);
    int acb  = (lane >> 4) << 4;
    int bg   = lane >> 3;
    int bn   = (bg >> 1) * 8 + (lane & 7);
    int bcb  = (bg & 1) << 4;

    for (int ch = 0; ch < NCH; ch++) {
        int cur = ch % STAGES;
        if (ch + 2 < NCH) load_chunk(ch + 2, (ch + 2) % STAGES);
        asm volatile("cp.async.commit_group;");
        asm volatile("cp.async.wait_group %0;" :: "n"(2));
        __syncthreads();

        uint32_t smA = sb + cur * STAGE_BYTES;
        uint32_t smB = smA + STAGE_A;
#pragma unroll
        for (int ks = 0; ks < 4; ks++) {
            uint32_t a[2][4];
#pragma unroll
            for (int am = 0; am < 2; am++) {
                int row = arow + am * 16;
                uint32_t addr = smA + row * 128 + (((ks * 32) + acb) ^ ((row & 7) << 4));
                ldsm4(a[am], addr);
            }
#pragma unroll
            for (int p = 0; p < 4; p++) {
                int n = wn + p * 16 + bn;
                uint32_t addr = smB + n * 128 + (((ks * 32) + bcb) ^ ((n & 7) << 4));
                uint32_t b[4];
                ldsm4(b, addr);
#pragma unroll
                for (int am = 0; am < 2; am++) {
                    mma16816(acc[am][2 * p],     a[am], b[0], b[1]);
                    mma16816(acc[am][2 * p + 1], a[am], b[2], b[3]);
                }
            }
        }
        __syncthreads();
    }

    // -------- epilogue: count s[i,j] > diag[i], j != i --------
    const float* Dg = g_diag[z];
    int* cnt = g_cnt[z];
#pragma unroll
    for (int am = 0; am < 2; am++) {
        int rlo = row0 + wm + am * 16 + (lane >> 2);
        int rhi = rlo + 8;
        float dlo = __ldg(&Dg[rlo]);
        float dhi = __ldg(&Dg[rhi]);
        int clo = 0, chi = 0;
#pragma unroll
        for (int j = 0; j < 8; j++) {
            int cb = col0 + wn + j * 8 + ((lane & 3) << 1);
            clo += (acc[am][j][0] > dlo && cb     != rlo) ? 1 : 0;
            clo += (acc[am][j][1] > dlo && cb + 1 != rlo) ? 1 : 0;
            chi += (acc[am][j][2] > dhi && cb     != rhi) ? 1 : 0;
            chi += (acc[am][j][3] > dhi && cb + 1 != rhi) ? 1 : 0;
        }
        clo += __shfl_xor_sync(0xffffffffu, clo, 1);
        clo += __shfl_xor_sync(0xffffffffu, clo, 2);
        chi += __shfl_xor_sync(0xffffffffu, chi, 1);
        chi += __shfl_xor_sync(0xffffffffu, chi, 2);
        if ((lane & 3) == 0) {
            atomicAdd(&cnt[rlo], clo);
            atomicAdd(&cnt[rhi], chi);
        }
    }
}

// ---------------- kernel 4: deterministic finalize ------------------------------
__global__ void finalize_kernel(float* __restrict__ out) {
    __shared__ float sm[16];
    int t = threadIdx.x;

    auto bsum = [&](float v) -> float {
#pragma unroll
        for (int m = 16; m; m >>= 1) v += __shfl_xor_sync(0xffffffffu, v, m);
        if ((t & 31) == 0) sm[t >> 5] = v;
        __syncthreads();
        float r = 0.f;
        if (t < 32) {
            r = (t < 16) ? sm[t] : 0.f;
#pragma unroll
            for (int m = 8; m; m >>= 1) r += __shfl_xor_sync(0xffffffffu, r, m);
        }
        __syncthreads();
        return r;
    };

    float s = 0.f;
    for (int i = t; i < N; i += 512) s += g_diag[0][i] + g_diag[1][i];
    float tot = bsum(s);
    if (t == 0) out[0] = -0.5f * tot / (float)N;

    for (int m = 0; m < 4; m++) {
        float S = 0.f, Q = 0.f;
#pragma unroll 8
        for (int ch = 0; ch < 64; ch++) {
            S += g_colsum[m][ch][t];
            Q += g_colsq[m][ch][t];
        }
        float var = (Q - S * S / (float)N) / (float)(N - 1);
        float sd = sqrtf(fmaxf(var, 0.f));
        float tots = bsum(sd);
        if (t == 0) out[1 + m] = tots / (float)C;
    }

    for (int z = 0; z < 2; z++) {
        const int* cnt = g_cnt[z];
        float c1 = 0.f, c5 = 0.f, c10 = 0.f, cm = 0.f;
        for (int i = t; i < N; i += 512) {
            int p = cnt[i];
            c1  += (p < 1)  ? 1.f : 0.f;
            c5  += (p < 5)  ? 1.f : 0.f;
            c10 += (p < 10) ? 1.f : 0.f;
            cm  += (float)p;
        }
        float t1 = bsum(c1);
        float t5 = bsum(c5);
        float t10 = bsum(c10);
        float tm = bsum(cm);
        if (t == 0) {
            out[5 + 4 * z + 0] = t1 / (float)N;
            out[5 + 4 * z + 1] = t5 / (float)N;
            out[5 + 4 * z + 2] = t10 / (float)N;
            out[5 + 4 * z + 3] = tm / (float)N;
        }
    }
}

// ---------------- launch ---------------------------------------------------------
extern "C" void kernel_launch(void* const* d_in, const int* in_sizes, int n_in,
                              void* d_out, int out_size) {
    const float* V  = (const float*)d_in[0];
    const float* T  = (const float*)d_in[1];
    const float* PV = (const float*)d_in[2];
    const float* PT = (const float*)d_in[3];

    // Idempotent, no static guard (harness forbids call-count-dependent behavior).
    cudaFuncSetAttribute(gemm_mma_kernel, cudaFuncAttributeMaxDynamicSharedMemorySize, SMEM_SIZE);

    zero_cnt_kernel<<<16, 512>>>();
    normalize_kernel<<<N, 128>>>(V, T, PV, PT);
    colstats_kernel<<<dim3(64, 4), 512>>>();
    gemm_mma_kernel<<<dim3(N / TN, N / TM, 2), 256, SMEM_SIZE>>>();
    finalize_kernel<<<1, 512>>>((float*)d_out);
}

// round 6
// speedup vs baseline: 2.2456x; 1.0520x over previous
#include <cuda_runtime.h>
#include <cuda_bf16.h>
#include <cstdint>

#define N 8192
#define C 512

// ---------------- scratch (device globals; no allocation allowed) ----------------
// Problem z=0: A=Vn, B=PTn (s1).  z=1: A=Tn, B=PVn (s2).
__device__ __nv_bfloat16 g_Ahi[2][N * C];
__device__ __nv_bfloat16 g_Alo[2][N * C];
__device__ __nv_bfloat16 g_Bhi[2][N * C];
__device__ __nv_bfloat16 g_Blo[2][N * C];
__device__ float g_diag[2][N];   // exact fp32 diagonals
__device__ int   g_cnt[2][N];
__device__ float g_colsum[4][64][C];
__device__ float g_colsq[4][64][C];

__device__ __forceinline__ uint32_t smem_u32(const void* p) {
    uint32_t a;
    asm("{ .reg .u64 t; cvta.to.shared.u64 t, %1; cvt.u32.u64 %0, t; }" : "=r"(a) : "l"(p));
    return a;
}

// ---------------- kernel 0: zero count accumulators (graph replays!) ------------
__global__ void zero_cnt_kernel() {
    int i = blockIdx.x * blockDim.x + threadIdx.x;
    if (i < N) { g_cnt[0][i] = 0; g_cnt[1][i] = 0; }
}

__device__ __forceinline__ float dot4(float4 a, float4 b) {
    return a.x * b.x + a.y * b.y + a.z * b.z + a.w * b.w;
}

__device__ __forceinline__ void split_store(__nv_bfloat16* hi, __nv_bfloat16* lo, size_t base,
                                            float4 y, float r) {
    float x0 = y.x * r, x1 = y.y * r, x2 = y.z * r, x3 = y.w * r;
    __nv_bfloat16 h0 = __float2bfloat16(x0), h1 = __float2bfloat16(x1);
    __nv_bfloat16 h2 = __float2bfloat16(x2), h3 = __float2bfloat16(x3);
    __nv_bfloat16 l0 = __float2bfloat16(x0 - __bfloat162float(h0));
    __nv_bfloat16 l1 = __float2bfloat16(x1 - __bfloat162float(h1));
    __nv_bfloat16 l2 = __float2bfloat16(x2 - __bfloat162float(h2));
    __nv_bfloat16 l3 = __float2bfloat16(x3 - __bfloat162float(h3));
    __nv_bfloat162 a, b;
    a.x = h0; a.y = h1; b.x = h2; b.y = h3;
    *(__nv_bfloat162*)(hi + base) = a;
    *(__nv_bfloat162*)(hi + base + 2) = b;
    a.x = l0; a.y = l1; b.x = l2; b.y = l3;
    *(__nv_bfloat162*)(lo + base) = a;
    *(__nv_bfloat162*)(lo + base + 2) = b;
}

// ---------------- kernel 1: normalize + split to bf16 hi/lo + exact diagonals ---
__global__ void normalize_kernel(const float* __restrict__ V, const float* __restrict__ T,
                                 const float* __restrict__ PV, const float* __restrict__ PT) {
    int row = blockIdx.x;
    int t   = threadIdx.x;
    size_t base = (size_t)row * C + 4 * t;

    float4 v  = *(const float4*)(V  + base);
    float4 tf = *(const float4*)(T  + base);
    float4 pv = *(const float4*)(PV + base);
    float4 pt = *(const float4*)(PT + base);

    float p0 = dot4(v, v),  p1 = dot4(tf, tf), p2 = dot4(pv, pv);
    float p3 = dot4(pt, pt), p4 = dot4(v, pt), p5 = dot4(tf, pv);

#pragma unroll
    for (int m = 16; m; m >>= 1) {
        p0 += __shfl_xor_sync(0xffffffffu, p0, m);
        p1 += __shfl_xor_sync(0xffffffffu, p1, m);
        p2 += __shfl_xor_sync(0xffffffffu, p2, m);
        p3 += __shfl_xor_sync(0xffffffffu, p3, m);
        p4 += __shfl_xor_sync(0xffffffffu, p4, m);
        p5 += __shfl_xor_sync(0xffffffffu, p5, m);
    }
    __shared__ float sm[4][6];
    int w = t >> 5;
    if ((t & 31) == 0) {
        sm[w][0] = p0; sm[w][1] = p1; sm[w][2] = p2;
        sm[w][3] = p3; sm[w][4] = p4; sm[w][5] = p5;
    }
    __syncthreads();
    float s0 = sm[0][0] + sm[1][0] + sm[2][0] + sm[3][0];
    float s1 = sm[0][1] + sm[1][1] + sm[2][1] + sm[3][1];
    float s2 = sm[0][2] + sm[1][2] + sm[2][2] + sm[3][2];
    float s3 = sm[0][3] + sm[1][3] + sm[2][3] + sm[3][3];
    float s4 = sm[0][4] + sm[1][4] + sm[2][4] + sm[3][4];
    float s5 = sm[0][5] + sm[1][5] + sm[2][5] + sm[3][5];

    float rv  = rsqrtf(s0);
    float rt_ = rsqrtf(s1);
    float rpv = rsqrtf(s2);
    float rpt = rsqrtf(s3);

    split_store(g_Ahi[0], g_Alo[0], base, v,  rv);   // Vn  (A of problem 0)
    split_store(g_Ahi[1], g_Alo[1], base, tf, rt_);  // Tn  (A of problem 1)
    split_store(g_Bhi[1], g_Blo[1], base, pv, rpv);  // PVn (B of problem 1)
    split_store(g_Bhi[0], g_Blo[0], base, pt, rpt);  // PTn (B of problem 0)

    if (t == 0) {
        g_diag[0][row] = s4 * rv  * rpt;  // v_n . p_t_n
        g_diag[1][row] = s5 * rt_ * rpv;  // t_n . p_v_n
    }
}

// ---------------- kernel 2: per-column partial sums for std (from hi+lo) --------
__global__ void colstats_kernel() {
    int mat = blockIdx.y, chunk = blockIdx.x, col = threadIdx.x;
    const __nv_bfloat16* hi;
    const __nv_bfloat16* lo;
    switch (mat) {
        case 0: hi = g_Ahi[0]; lo = g_Alo[0]; break;  // v_feat
        case 1: hi = g_Ahi[1]; lo = g_Alo[1]; break;  // t_feat
        case 2: hi = g_Bhi[1]; lo = g_Blo[1]; break;  // p_v
        default: hi = g_Bhi[0]; lo = g_Blo[0]; break; // p_t
    }
    float s = 0.f, q = 0.f;
    int r0 = chunk * 128;
#pragma unroll 4
    for (int r = r0; r < r0 + 128; r++) {
        size_t idx = (size_t)r * C + col;
        float x = __bfloat162float(hi[idx]) + __bfloat162float(lo[idx]);
        s += x;
        q += x * x;
    }
    g_colsum[mat][chunk][col] = s;
    g_colsq[mat][chunk][col]  = q;
}

// ---------------- kernel 3: warp-MMA bf16 GEMM + fused rank-count epilogue ------
// C[i,j] = A[i,:].B[j,:], 3 hi/lo split segments, fp32 accumulation in registers.
// 128x128 tile, BK=64 (128B rows, swizzled), 4-stage cp.async ring, 512 threads,
// 16 warps in a 4x4 grid (32x32 warp tile), ONE barrier per chunk with the
// prefetch issued AFTER the barrier (so the write to stage (ch-1)&3 is ordered
// after all reads of it from iteration ch-1).
#define TM 128
#define TN 128
#define TK 64
#define STAGES 4
#define NTHR 512
#define STAGE_A (TM * 128)
#define STAGE_B (TN * 128)
#define STAGE_BYTES (STAGE_A + STAGE_B)   // 32768
#define SMEM_SIZE (STAGES * STAGE_BYTES)  // 131072
#define NCH 24                            // 3 segments * 8 k-chunks

__device__ __forceinline__ void ldsm4(uint32_t* r, uint32_t addr) {
    asm volatile("ldmatrix.sync.aligned.m8n8.x4.shared.b16 {%0,%1,%2,%3}, [%4];"
                 : "=r"(r[0]), "=r"(r[1]), "=r"(r[2]), "=r"(r[3]) : "r"(addr));
}
__device__ __forceinline__ void mma16816(float* d, const uint32_t* a, uint32_t b0, uint32_t b1) {
    asm volatile(
        "mma.sync.aligned.m16n8k16.row.col.f32.bf16.bf16.f32 "
        "{%0,%1,%2,%3}, {%4,%5,%6,%7}, {%8,%9}, {%0,%1,%2,%3};"
        : "+f"(d[0]), "+f"(d[1]), "+f"(d[2]), "+f"(d[3])
        : "r"(a[0]), "r"(a[1]), "r"(a[2]), "r"(a[3]), "r"(b0), "r"(b1));
}

__device__ __forceinline__ void load_tile(uint32_t smem_dst, const __nv_bfloat16* __restrict__ src,
                                          int row0, int kk, int tid) {
#pragma unroll
    for (int i = 0; i < 2; i++) {
        int idx = tid + i * NTHR;
        int r  = idx >> 3;
        int cb = (idx & 7) << 4;
        uint32_t dst = smem_dst + r * 128 + (cb ^ ((r & 7) << 4));
        const void* s = (const char*)(src + (size_t)(row0 + r) * C + kk) + cb;
        asm volatile("cp.async.cg.shared.global [%0], [%1], 16;" :: "r"(dst), "l"(s));
    }
}

__global__ void __launch_bounds__(NTHR, 1) gemm_mma_kernel() {
    extern __shared__ char smem[];
    uint32_t sb = smem_u32(smem);
    int tid = threadIdx.x, lane = tid & 31, wid = tid >> 5;
    int z = blockIdx.z;
    int row0 = blockIdx.y * TM;
    int col0 = blockIdx.x * TN;

    const __nv_bfloat16* Ahi = g_Ahi[z];
    const __nv_bfloat16* Alo = g_Alo[z];
    const __nv_bfloat16* Bhi = g_Bhi[z];
    const __nv_bfloat16* Blo = g_Blo[z];

    auto load_chunk = [&](int ch, int stage) {
        int seg = ch >> 3;
        int kk  = (ch & 7) * TK;
        const __nv_bfloat16* As = (seg < 2)  ? Ahi : Alo;
        const __nv_bfloat16* Bs = (seg == 1) ? Blo : Bhi;
        uint32_t s = sb + stage * STAGE_BYTES;
        load_tile(s, As, row0, kk, tid);
        load_tile(s + STAGE_A, Bs, col0, kk, tid);
    };

    int wm = (wid >> 2) * 32;   // warp M offset (4 rows of warps)
    int wn = (wid & 3) * 32;    // warp N offset (4 cols of warps)

    float acc[2][4][4];
#pragma unroll
    for (int a = 0; a < 2; a++)
#pragma unroll
        for (int j = 0; j < 4; j++)
#pragma unroll
            for (int q = 0; q < 4; q++) acc[a][j][q] = 0.f;

    // prologue: chunks 0..2 into stages 0..2 (3 commit groups in flight)
    load_chunk(0, 0);
    asm volatile("cp.async.commit_group;");
    load_chunk(1, 1);
    asm volatile("cp.async.commit_group;");
    load_chunk(2, 2);
    asm volatile("cp.async.commit_group;");

    // ldmatrix address components (loop-invariant)
    int arow = wm + (lane & 15);
    int acb  = (lane >> 4) << 4;
    int bg   = lane >> 3;
    int bn   = (bg >> 1) * 8 + (lane & 7);
    int bcb  = (bg & 1) << 4;

    for (int ch = 0; ch < NCH; ch++) {
        int cur = ch & (STAGES - 1);
        // chunk ch's group complete (3 groups in flight -> let 2 remain)
        asm volatile("cp.async.wait_group %0;" :: "n"(2));
        // orders: (a) all warps see chunk ch's data; (b) all warps finished
        // reading stage (ch-1)&3 in iteration ch-1 -> safe to overwrite below.
        __syncthreads();
        if (ch + 3 < NCH) load_chunk(ch + 3, (ch + 3) & (STAGES - 1));
        asm volatile("cp.async.commit_group;");

        uint32_t smA = sb + cur * STAGE_BYTES;
        uint32_t smB = smA + STAGE_A;
#pragma unroll
        for (int ks = 0; ks < 4; ks++) {
            uint32_t a[2][4];
#pragma unroll
            for (int am = 0; am < 2; am++) {
                int row = arow + am * 16;
                uint32_t addr = smA + row * 128 + (((ks * 32) + acb) ^ ((row & 7) << 4));
                ldsm4(a[am], addr);
            }
#pragma unroll
            for (int p = 0; p < 2; p++) {
                int n = wn + p * 16 + bn;
                uint32_t addr = smB + n * 128 + (((ks * 32) + bcb) ^ ((n & 7) << 4));
                uint32_t b[4];
                ldsm4(b, addr);
#pragma unroll
                for (int am = 0; am < 2; am++) {
                    mma16816(acc[am][2 * p],     a[am], b[0], b[1]);
                    mma16816(acc[am][2 * p + 1], a[am], b[2], b[3]);
                }
            }
        }
    }

    // -------- epilogue: count s[i,j] > diag[i], j != i --------
    const float* Dg = g_diag[z];
    int* cnt = g_cnt[z];
#pragma unroll
    for (int am = 0; am < 2; am++) {
        int rlo = row0 + wm + am * 16 + (lane >> 2);
        int rhi = rlo + 8;
        float dlo = __ldg(&Dg[rlo]);
        float dhi = __ldg(&Dg[rhi]);
        int clo = 0, chi = 0;
#pragma unroll
        for (int j = 0; j < 4; j++) {
            int cb = col0 + wn + j * 8 + ((lane & 3) << 1);
            clo += (acc[am][j][0] > dlo && cb     != rlo) ? 1 : 0;
            clo += (acc[am][j][1] > dlo && cb + 1 != rlo) ? 1 : 0;
            chi += (acc[am][j][2] > dhi && cb     != rhi) ? 1 : 0;
            chi += (acc[am][j][3] > dhi && cb + 1 != rhi) ? 1 : 0;
        }
        clo += __shfl_xor_sync(0xffffffffu, clo, 1);
        clo += __shfl_xor_sync(0xffffffffu, clo, 2);
        chi += __shfl_xor_sync(0xffffffffu, chi, 1);
        chi += __shfl_xor_sync(0xffffffffu, chi, 2);
        if ((lane & 3) == 0) {
            atomicAdd(&cnt[rlo], clo);
            atomicAdd(&cnt[rhi], chi);
        }
    }
}

// ---------------- kernel 4: deterministic finalize ------------------------------
__global__ void finalize_kernel(float* __restrict__ out) {
    __shared__ float sm[16];
    int t = threadIdx.x;

    auto bsum = [&](float v) -> float {
#pragma unroll
        for (int m = 16; m; m >>= 1) v += __shfl_xor_sync(0xffffffffu, v, m);
        if ((t & 31) == 0) sm[t >> 5] = v;
        __syncthreads();
        float r = 0.f;
        if (t < 32) {
            r = (t < 16) ? sm[t] : 0.f;
#pragma unroll
            for (int m = 8; m; m >>= 1) r += __shfl_xor_sync(0xffffffffu, r, m);
        }
        __syncthreads();
        return r;
    };

    float s = 0.f;
    for (int i = t; i < N; i += 512) s += g_diag[0][i] + g_diag[1][i];
    float tot = bsum(s);
    if (t == 0) out[0] = -0.5f * tot / (float)N;

    for (int m = 0; m < 4; m++) {
        float S = 0.f, Q = 0.f;
#pragma unroll 8
        for (int ch = 0; ch < 64; ch++) {
            S += g_colsum[m][ch][t];
            Q += g_colsq[m][ch][t];
        }
        float var = (Q - S * S / (float)N) / (float)(N - 1);
        float sd = sqrtf(fmaxf(var, 0.f));
        float tots = bsum(sd);
        if (t == 0) out[1 + m] = tots / (float)C;
    }

    for (int z = 0; z < 2; z++) {
        const int* cnt = g_cnt[z];
        float c1 = 0.f, c5 = 0.f, c10 = 0.f, cm = 0.f;
        for (int i = t; i < N; i += 512) {
            int p = cnt[i];
            c1  += (p < 1)  ? 1.f : 0.f;
            c5  += (p < 5)  ? 1.f : 0.f;
            c10 += (p < 10) ? 1.f : 0.f;
            cm  += (float)p;
        }
        float t1 = bsum(c1);
        float t5 = bsum(c5);
        float t10 = bsum(c10);
        float tm = bsum(cm);
        if (t == 0) {
            out[5 + 4 * z + 0] = t1 / (float)N;
            out[5 + 4 * z + 1] = t5 / (float)N;
            out[5 + 4 * z + 2] = t10 / (float)N;
            out[5 + 4 * z + 3] = tm / (float)N;
        }
    }
}

// ---------------- launch ---------------------------------------------------------
extern "C" void kernel_launch(void* const* d_in, const int* in_sizes, int n_in,
                              void* d_out, int out_size) {
    const float* V  = (const float*)d_in[0];
    const float* T  = (const float*)d_in[1];
    const float* PV = (const float*)d_in[2];
    const float* PT = (const float*)d_in[3];

    // Idempotent, no static guard (harness forbids call-count-dependent behavior).
    cudaFuncSetAttribute(gemm_mma_kernel, cudaFuncAttributeMaxDynamicSharedMemorySize, SMEM_SIZE);

    zero_cnt_kernel<<<16, 512>>>();
    normalize_kernel<<<N, 128>>>(V, T, PV, PT);
    colstats_kernel<<<dim3(64, 4), 512>>>();
    gemm_mma_kernel<<<dim3(N / TN, N / TM, 2), NTHR, SMEM_SIZE>>>();
    finalize_kernel<<<1, 512>>>((float*)d_out);
}

// round 9
// speedup vs baseline: 2.9028x; 1.2927x over previous
#include <cuda_runtime.h>
#include <cuda_bf16.h>
#include <cstdint>

#define N 8192
#define C 512

// ---------------- scratch (device globals; no allocation allowed) ----------------
// Problem z=0: A=Vn, B=PTn (s1).  z=1: A=Tn, B=PVn (s2).
__device__ __nv_bfloat16 g_Ahi[2][N * C];
__device__ __nv_bfloat16 g_Alo[2][N * C];
__device__ __nv_bfloat16 g_Bhi[2][N * C];
__device__ __nv_bfloat16 g_Blo[2][N * C];
__device__ float g_diag[2][N];   // exact fp32 diagonals
__device__ int   g_cnt[2][N];
__device__ float g_colsum[4][64][C];
__device__ float g_colsq[4][64][C];

__device__ __forceinline__ uint32_t smem_u32(const void* p) {
    uint32_t a;
    asm("{ .reg .u64 t; cvta.to.shared.u64 t, %1; cvt.u32.u64 %0, t; }" : "=r"(a) : "l"(p));
    return a;
}

// ---------------- kernel 0: zero count accumulators (graph replays!) ------------
__global__ void zero_cnt_kernel() {
    int i = blockIdx.x * blockDim.x + threadIdx.x;
    if (i < N) { g_cnt[0][i] = 0; g_cnt[1][i] = 0; }
}

__device__ __forceinline__ float dot4(float4 a, float4 b) {
    return a.x * b.x + a.y * b.y + a.z * b.z + a.w * b.w;
}

__device__ __forceinline__ void split_store(__nv_bfloat16* hi, __nv_bfloat16* lo, size_t base,
                                            float4 y, float r) {
    float x0 = y.x * r, x1 = y.y * r, x2 = y.z * r, x3 = y.w * r;
    __nv_bfloat16 h0 = __float2bfloat16(x0), h1 = __float2bfloat16(x1);
    __nv_bfloat16 h2 = __float2bfloat16(x2), h3 = __float2bfloat16(x3);
    __nv_bfloat16 l0 = __float2bfloat16(x0 - __bfloat162float(h0));
    __nv_bfloat16 l1 = __float2bfloat16(x1 - __bfloat162float(h1));
    __nv_bfloat16 l2 = __float2bfloat16(x2 - __bfloat162float(h2));
    __nv_bfloat16 l3 = __float2bfloat16(x3 - __bfloat162float(h3));
    __nv_bfloat162 a, b;
    a.x = h0; a.y = h1; b.x = h2; b.y = h3;
    *(__nv_bfloat162*)(hi + base) = a;
    *(__nv_bfloat162*)(hi + base + 2) = b;
    a.x = l0; a.y = l1; b.x = l2; b.y = l3;
    *(__nv_bfloat162*)(lo + base) = a;
    *(__nv_bfloat162*)(lo + base + 2) = b;
}

// ---------------- kernel 1: normalize + split to bf16 hi/lo + exact diagonals ---
__global__ void normalize_kernel(const float* __restrict__ V, const float* __restrict__ T,
                                 const float* __restrict__ PV, const float* __restrict__ PT) {
    int row = blockIdx.x;
    int t   = threadIdx.x;
    size_t base = (size_t)row * C + 4 * t;

    float4 v  = *(const float4*)(V  + base);
    float4 tf = *(const float4*)(T  + base);
    float4 pv = *(const float4*)(PV + base);
    float4 pt = *(const float4*)(PT + base);

    float p0 = dot4(v, v),  p1 = dot4(tf, tf), p2 = dot4(pv, pv);
    float p3 = dot4(pt, pt), p4 = dot4(v, pt), p5 = dot4(tf, pv);

#pragma unroll
    for (int m = 16; m; m >>= 1) {
        p0 += __shfl_xor_sync(0xffffffffu, p0, m);
        p1 += __shfl_xor_sync(0xffffffffu, p1, m);
        p2 += __shfl_xor_sync(0xffffffffu, p2, m);
        p3 += __shfl_xor_sync(0xffffffffu, p3, m);
        p4 += __shfl_xor_sync(0xffffffffu, p4, m);
        p5 += __shfl_xor_sync(0xffffffffu, p5, m);
    }
    __shared__ float sm[4][6];
    int w = t >> 5;
    if ((t & 31) == 0) {
        sm[w][0] = p0; sm[w][1] = p1; sm[w][2] = p2;
        sm[w][3] = p3; sm[w][4] = p4; sm[w][5] = p5;
    }
    __syncthreads();
    float s0 = sm[0][0] + sm[1][0] + sm[2][0] + sm[3][0];
    float s1 = sm[0][1] + sm[1][1] + sm[2][1] + sm[3][1];
    float s2 = sm[0][2] + sm[1][2] + sm[2][2] + sm[3][2];
    float s3 = sm[0][3] + sm[1][3] + sm[2][3] + sm[3][3];
    float s4 = sm[0][4] + sm[1][4] + sm[2][4] + sm[3][4];
    float s5 = sm[0][5] + sm[1][5] + sm[2][5] + sm[3][5];

    float rv  = rsqrtf(s0);
    float rt_ = rsqrtf(s1);
    float rpv = rsqrtf(s2);
    float rpt = rsqrtf(s3);

    split_store(g_Ahi[0], g_Alo[0], base, v,  rv);   // Vn  (A of problem 0)
    split_store(g_Ahi[1], g_Alo[1], base, tf, rt_);  // Tn  (A of problem 1)
    split_store(g_Bhi[1], g_Blo[1], base, pv, rpv);  // PVn (B of problem 1)
    split_store(g_Bhi[0], g_Blo[0], base, pt, rpt);  // PTn (B of problem 0)

    if (t == 0) {
        g_diag[0][row] = s4 * rv  * rpt;  // v_n . p_t_n
        g_diag[1][row] = s5 * rt_ * rpv;  // t_n . p_v_n
    }
}

// ---------------- kernel 2: per-column partial sums for std (from hi+lo) --------
__global__ void colstats_kernel() {
    int mat = blockIdx.y, chunk = blockIdx.x, col = threadIdx.x;
    const __nv_bfloat16* hi;
    const __nv_bfloat16* lo;
    switch (mat) {
        case 0: hi = g_Ahi[0]; lo = g_Alo[0]; break;  // v_feat
        case 1: hi = g_Ahi[1]; lo = g_Alo[1]; break;  // t_feat
        case 2: hi = g_Bhi[1]; lo = g_Blo[1]; break;  // p_v
        default: hi = g_Bhi[0]; lo = g_Blo[0]; break; // p_t
    }
    float s = 0.f, q = 0.f;
    int r0 = chunk * 128;
#pragma unroll 4
    for (int r = r0; r < r0 + 128; r++) {
        size_t idx = (size_t)r * C + col;
        float x = __bfloat162float(hi[idx]) + __bfloat162float(lo[idx]);
        s += x;
        q += x * x;
    }
    g_colsum[mat][chunk][col] = s;
    g_colsq[mat][chunk][col]  = q;
}

// ---------------- kernel 3: warp-MMA bf16 GEMM + fused rank-count epilogue ------
// C[i,j] = A[i,:].B[j,:], 3 hi/lo split segments, fp32 accumulation in registers.
// 128x128 CTA tile, BK=64 (128B rows, swizzled), 3-stage cp.async ring,
// 256 threads, 8 warps in a 2x4 grid (64x32 warp tile), 2 CTAs/SM,
// one barrier per chunk with prefetch issued AFTER the barrier.
#define TM 128
#define TN 128
#define TK 64
#define STAGES 3
#define NTHR 256
#define STAGE_A (TM * 128)
#define STAGE_B (TN * 128)
#define STAGE_BYTES (STAGE_A + STAGE_B)   // 32768
#define SMEM_SIZE (STAGES * STAGE_BYTES)  // 98304
#define NCH 24                            // 3 segments * 8 k-chunks

__device__ __forceinline__ void ldsm4(uint32_t* r, uint32_t addr) {
    asm volatile("ldmatrix.sync.aligned.m8n8.x4.shared.b16 {%0,%1,%2,%3}, [%4];"
                 : "=r"(r[0]), "=r"(r[1]), "=r"(r[2]), "=r"(r[3]) : "r"(addr));
}
__device__ __forceinline__ void mma16816(float* d, const uint32_t* a, uint32_t b0, uint32_t b1) {
    asm volatile(
        "mma.sync.aligned.m16n8k16.row.col.f32.bf16.bf16.f32 "
        "{%0,%1,%2,%3}, {%4,%5,%6,%7}, {%8,%9}, {%0,%1,%2,%3};"
        : "+f"(d[0]), "+f"(d[1]), "+f"(d[2]), "+f"(d[3])
        : "r"(a[0]), "r"(a[1]), "r"(a[2]), "r"(a[3]), "r"(b0), "r"(b1));
}

__device__ __forceinline__ void load_tile(uint32_t smem_dst, const __nv_bfloat16* __restrict__ src,
                                          int row0, int kk, int tid) {
#pragma unroll
    for (int i = 0; i < 4; i++) {
        int idx = tid + i * NTHR;
        int r  = idx >> 3;
        int cb = (idx & 7) << 4;
        uint32_t dst = smem_dst + r * 128 + (cb ^ ((r & 7) << 4));
        const void* s = (const char*)(src + (size_t)(row0 + r) * C + kk) + cb;
        asm volatile("cp.async.cg.shared.global [%0], [%1], 16;" :: "r"(dst), "l"(s));
    }
}

__global__ void __launch_bounds__(NTHR, 2) gemm_mma_kernel() {
    extern __shared__ char smem[];
    uint32_t sb = smem_u32(smem);
    int tid = threadIdx.x, lane = tid & 31, wid = tid >> 5;
    int z = blockIdx.z;
    int row0 = blockIdx.y * TM;
    int col0 = blockIdx.x * TN;

    const __nv_bfloat16* Ahi = g_Ahi[z];
    const __nv_bfloat16* Alo = g_Alo[z];
    const __nv_bfloat16* Bhi = g_Bhi[z];
    const __nv_bfloat16* Blo = g_Blo[z];

    auto load_chunk = [&](int ch, int stage) {
        int seg = ch >> 3;
        int kk  = (ch & 7) * TK;
        const __nv_bfloat16* As = (seg < 2)  ? Ahi : Alo;
        const __nv_bfloat16* Bs = (seg == 1) ? Blo : Bhi;
        uint32_t s = sb + stage * STAGE_BYTES;
        load_tile(s, As, row0, kk, tid);
        load_tile(s + STAGE_A, Bs, col0, kk, tid);
    };

    int wm = (wid >> 2) * 64;   // warp M offset (2 row groups)
    int wn = (wid & 3) * 32;    // warp N offset (4 col groups)

    float acc[4][4][4];         // [m16 sub][n8 sub][quad regs]
#pragma unroll
    for (int a = 0; a < 4; a++)
#pragma unroll
        for (int j = 0; j < 4; j++)
#pragma unroll
            for (int q = 0; q < 4; q++) acc[a][j][q] = 0.f;

    // prologue: chunks 0,1 into stages 0,1 (2 commit groups in flight)
    load_chunk(0, 0);
    asm volatile("cp.async.commit_group;");
    load_chunk(1, 1);
    asm volatile("cp.async.commit_group;");

    // ldmatrix address components (loop-invariant)
    int arow = wm + (lane & 15);
    int acb  = (lane >> 4) << 4;
    int bg   = lane >> 3;
    int bn   = (bg >> 1) * 8 + (lane & 7);
    int bcb  = (bg & 1) << 4;

    int cur = 0, pre = 2;
    for (int ch = 0; ch < NCH; ch++) {
        // chunk ch's group complete (2 groups in flight -> let 1 remain)
        asm volatile("cp.async.wait_group %0;" :: "n"(1));
        // orders: (a) all warps see chunk ch's data; (b) all warps finished
        // reading stage (ch-1)%3 in iteration ch-1 -> safe to overwrite below.
        __syncthreads();
        if (ch + 2 < NCH) load_chunk(ch + 2, pre);
        asm volatile("cp.async.commit_group;");

        uint32_t smA = sb + cur * STAGE_BYTES;
        uint32_t smB = smA + STAGE_A;
#pragma unroll
        for (int ks = 0; ks < 4; ks++) {
            uint32_t a[4][4];
#pragma unroll
            for (int am = 0; am < 4; am++) {
                int row = arow + am * 16;
                uint32_t addr = smA + row * 128 + (((ks * 32) + acb) ^ ((row & 7) << 4));
                ldsm4(a[am], addr);
            }
#pragma unroll
            for (int p = 0; p < 2; p++) {
                int n = wn + p * 16 + bn;
                uint32_t addr = smB + n * 128 + (((ks * 32) + bcb) ^ ((n & 7) << 4));
                uint32_t b[4];
                ldsm4(b, addr);
#pragma unroll
                for (int am = 0; am < 4; am++) {
                    mma16816(acc[am][2 * p],     a[am], b[0], b[1]);
                    mma16816(acc[am][2 * p + 1], a[am], b[2], b[3]);
                }
            }
        }
        if (++cur == STAGES) cur = 0;
        if (++pre == STAGES) pre = 0;
    }

    // -------- epilogue: count s[i,j] > diag[i], j != i --------
    const float* Dg = g_diag[z];
    int* cnt = g_cnt[z];
#pragma unroll
    for (int am = 0; am < 4; am++) {
        int rlo = row0 + wm + am * 16 + (lane >> 2);
        int rhi = rlo + 8;
        float dlo = __ldg(&Dg[rlo]);
        float dhi = __ldg(&Dg[rhi]);
        int clo = 0, chi = 0;
#pragma unroll
        for (int j = 0; j < 4; j++) {
            int cb = col0 + wn + j * 8 + ((lane & 3) << 1);
            clo += (acc[am][j][0] > dlo && cb     != rlo) ? 1 : 0;
            clo += (acc[am][j][1] > dlo && cb + 1 != rlo) ? 1 : 0;
            chi += (acc[am][j][2] > dhi && cb     != rhi) ? 1 : 0;
            chi += (acc[am][j][3] > dhi && cb + 1 != rhi) ? 1 : 0;
        }
        clo += __shfl_xor_sync(0xffffffffu, clo, 1);
        clo += __shfl_xor_sync(0xffffffffu, clo, 2);
        chi += __shfl_xor_sync(0xffffffffu, chi, 1);
        chi += __shfl_xor_sync(0xffffffffu, chi, 2);
        if ((lane & 3) == 0) {
            atomicAdd(&cnt[rlo], clo);
            atomicAdd(&cnt[rhi], chi);
        }
    }
}

// ---------------- kernel 4: deterministic finalize ------------------------------
__global__ void finalize_kernel(float* __restrict__ out) {
    __shared__ float sm[16];
    int t = threadIdx.x;

    auto bsum = [&](float v) -> float {
#pragma unroll
        for (int m = 16; m; m >>= 1) v += __shfl_xor_sync(0xffffffffu, v, m);
        if ((t & 31) == 0) sm[t >> 5] = v;
        __syncthreads();
        float r = 0.f;
        if (t < 32) {
            r = (t < 16) ? sm[t] : 0.f;
#pragma unroll
            for (int m = 8; m; m >>= 1) r += __shfl_xor_sync(0xffffffffu, r, m);
        }
        __syncthreads();
        return r;
    };

    float s = 0.f;
    for (int i = t; i < N; i += 512) s += g_diag[0][i] + g_diag[1][i];
    float tot = bsum(s);
    if (t == 0) out[0] = -0.5f * tot / (float)N;

    for (int m = 0; m < 4; m++) {
        float S = 0.f, Q = 0.f;
#pragma unroll 8
        for (int ch = 0; ch < 64; ch++) {
            S += g_colsum[m][ch][t];
            Q += g_colsq[m][ch][t];
        }
        float var = (Q - S * S / (float)N) / (float)(N - 1);
        float sd = sqrtf(fmaxf(var, 0.f));
        float tots = bsum(sd);
        if (t == 0) out[1 + m] = tots / (float)C;
    }

    for (int z = 0; z < 2; z++) {
        const int* cnt = g_cnt[z];
        float c1 = 0.f, c5 = 0.f, c10 = 0.f, cm = 0.f;
        for (int i = t; i < N; i += 512) {
            int p = cnt[i];
            c1  += (p < 1)  ? 1.f : 0.f;
            c5  += (p < 5)  ? 1.f : 0.f;
            c10 += (p < 10) ? 1.f : 0.f;
            cm  += (float)p;
        }
        float t1 = bsum(c1);
        float t5 = bsum(c5);
        float t10 = bsum(c10);
        float tm = bsum(cm);
        if (t == 0) {
            out[5 + 4 * z + 0] = t1 / (float)N;
            out[5 + 4 * z + 1] = t5 / (float)N;
            out[5 + 4 * z + 2] = t10 / (float)N;
            out[5 + 4 * z + 3] = tm / (float)N;
        }
    }
}

// ---------------- launch ---------------------------------------------------------
extern "C" void kernel_launch(void* const* d_in, const int* in_sizes, int n_in,
                              void* d_out, int out_size) {
    const float* V  = (const float*)d_in[0];
    const float* T  = (const float*)d_in[1];
    const float* PV = (const float*)d_in[2];
    const float* PT = (const float*)d_in[3];

    // Idempotent, no static guard (harness forbids call-count-dependent behavior).
    cudaFuncSetAttribute(gemm_mma_kernel, cudaFuncAttributeMaxDynamicSharedMemorySize, SMEM_SIZE);

    zero_cnt_kernel<<<16, 512>>>();
    normalize_kernel<<<N, 128>>>(V, T, PV, PT);
    colstats_kernel<<<dim3(64, 4), 512>>>();
    gemm_mma_kernel<<<dim3(N / TN, N / TM, 2), NTHR, SMEM_SIZE>>>();
    finalize_kernel<<<1, 512>>>((float*)d_out);
}

// round 10
// speedup vs baseline: 4.5456x; 1.5659x over previous
#include <cuda_runtime.h>
#include <cuda_fp16.h>
#include <cstdint>

#define N 8192
#define C 512
#define THETA 1.5e-4f
#define WCAP (1 << 22)      // global worklist capacity (16 MB)
#define LCAP 8192           // per-CTA smem worklist capacity

// ---------------- scratch (device globals; no allocation allowed) ----------------
// Problem z=0: A=Vn, B=PTn (s1).  z=1: A=Tn, B=PVn (s2).
__device__ __half g_Ah[2][N * C];     // fp16 normalized A (pass-1 GEMM)
__device__ __half g_Bh[2][N * C];     // fp16 normalized B
__device__ float  g_Af[2][N * C];     // fp32 normalized A (pass-2 exact dots)
__device__ float  g_Bf[2][N * C];     // fp32 normalized B
__device__ float  g_diag[2][N];       // exact fp32 diagonals
__device__ int    g_cnt[2][N];
__device__ int    g_nwork;
__device__ uint32_t g_work[WCAP];     // packed (z<<26)|(i<<13)|j
__device__ float g_colsum[4][64][C];
__device__ float g_colsq[4][64][C];

__device__ __forceinline__ uint32_t smem_u32(const void* p) {
    uint32_t a;
    asm("{ .reg .u64 t; cvta.to.shared.u64 t, %1; cvt.u32.u64 %0, t; }" : "=r"(a) : "l"(p));
    return a;
}

// ---------------- kernel 0: zero count accumulators (graph replays!) ------------
__global__ void zero_cnt_kernel() {
    int i = blockIdx.x * blockDim.x + threadIdx.x;
    if (i < N) { g_cnt[0][i] = 0; g_cnt[1][i] = 0; }
    if (i == 0) g_nwork = 0;
}

__device__ __forceinline__ float dot4(float4 a, float4 b) {
    return a.x * b.x + a.y * b.y + a.z * b.z + a.w * b.w;
}

__device__ __forceinline__ void store_nf(__half* h, float* f, size_t base, float4 y, float r) {
    float4 o = make_float4(y.x * r, y.y * r, y.z * r, y.w * r);
    *(float4*)(f + base) = o;
    *(__half2*)(h + base)     = __floats2half2_rn(o.x, o.y);
    *(__half2*)(h + base + 2) = __floats2half2_rn(o.z, o.w);
}

// ---------------- kernel 1: normalize -> fp16 + fp32 copies + exact diagonals ---
__global__ void normalize_kernel(const float* __restrict__ V, const float* __restrict__ T,
                                 const float* __restrict__ PV, const float* __restrict__ PT) {
    int row = blockIdx.x;
    int t   = threadIdx.x;
    size_t base = (size_t)row * C + 4 * t;

    float4 v  = *(const float4*)(V  + base);
    float4 tf = *(const float4*)(T  + base);
    float4 pv = *(const float4*)(PV + base);
    float4 pt = *(const float4*)(PT + base);

    float p0 = dot4(v, v),  p1 = dot4(tf, tf), p2 = dot4(pv, pv);
    float p3 = dot4(pt, pt), p4 = dot4(v, pt), p5 = dot4(tf, pv);

#pragma unroll
    for (int m = 16; m; m >>= 1) {
        p0 += __shfl_xor_sync(0xffffffffu, p0, m);
        p1 += __shfl_xor_sync(0xffffffffu, p1, m);
        p2 += __shfl_xor_sync(0xffffffffu, p2, m);
        p3 += __shfl_xor_sync(0xffffffffu, p3, m);
        p4 += __shfl_xor_sync(0xffffffffu, p4, m);
        p5 += __shfl_xor_sync(0xffffffffu, p5, m);
    }
    __shared__ float sm[4][6];
    int w = t >> 5;
    if ((t & 31) == 0) {
        sm[w][0] = p0; sm[w][1] = p1; sm[w][2] = p2;
        sm[w][3] = p3; sm[w][4] = p4; sm[w][5] = p5;
    }
    __syncthreads();
    float s0 = sm[0][0] + sm[1][0] + sm[2][0] + sm[3][0];
    float s1 = sm[0][1] + sm[1][1] + sm[2][1] + sm[3][1];
    float s2 = sm[0][2] + sm[1][2] + sm[2][2] + sm[3][2];
    float s3 = sm[0][3] + sm[1][3] + sm[2][3] + sm[3][3];
    float s4 = sm[0][4] + sm[1][4] + sm[2][4] + sm[3][4];
    float s5 = sm[0][5] + sm[1][5] + sm[2][5] + sm[3][5];

    float rv  = rsqrtf(s0);
    float rt_ = rsqrtf(s1);
    float rpv = rsqrtf(s2);
    float rpt = rsqrtf(s3);

    store_nf(g_Ah[0], g_Af[0], base, v,  rv);   // Vn  (A of problem 0)
    store_nf(g_Ah[1], g_Af[1], base, tf, rt_);  // Tn  (A of problem 1)
    store_nf(g_Bh[1], g_Bf[1], base, pv, rpv);  // PVn (B of problem 1)
    store_nf(g_Bh[0], g_Bf[0], base, pt, rpt);  // PTn (B of problem 0)

    if (t == 0) {
        g_diag[0][row] = s4 * rv  * rpt;  // v_n . p_t_n
        g_diag[1][row] = s5 * rt_ * rpv;  // t_n . p_v_n
    }
}

// ---------------- kernel 2: per-column partial sums for std (fp32 copies) -------
__global__ void colstats_kernel() {
    int mat = blockIdx.y, chunk = blockIdx.x, col = threadIdx.x;
    const float* M;
    switch (mat) {
        case 0: M = g_Af[0]; break;  // v_feat
        case 1: M = g_Af[1]; break;  // t_feat
        case 2: M = g_Bf[1]; break;  // p_v
        default: M = g_Bf[0]; break; // p_t
    }
    float s = 0.f, q = 0.f;
    int r0 = chunk * 128;
#pragma unroll 4
    for (int r = r0; r < r0 + 128; r++) {
        float x = M[(size_t)r * C + col];
        s += x;
        q += x * x;
    }
    g_colsum[mat][chunk][col] = s;
    g_colsq[mat][chunk][col]  = q;
}

// ---------------- kernel 3: fp16 warp-MMA GEMM + threshold-count epilogue -------
// Single fp16 segment (K=512). Count v > d+THETA; |v-d|<=THETA -> worklist.
// 128x128 CTA tile, BK=64, 3-stage cp.async ring, 256 thr, 8 warps (64x32 tiles),
// 2 CTAs/SM, one barrier per chunk with prefetch after the barrier.
#define TM 128
#define TN 128
#define TK 64
#define STAGES 3
#define NTHR 256
#define STAGE_A (TM * 128)
#define STAGE_B (TN * 128)
#define STAGE_BYTES (STAGE_A + STAGE_B)   // 32768
#define SMEM_SIZE (STAGES * STAGE_BYTES)  // 98304
#define NCH 8                             // K=512 / 64

__device__ __forceinline__ void ldsm4(uint32_t* r, uint32_t addr) {
    asm volatile("ldmatrix.sync.aligned.m8n8.x4.shared.b16 {%0,%1,%2,%3}, [%4];"
                 : "=r"(r[0]), "=r"(r[1]), "=r"(r[2]), "=r"(r[3]) : "r"(addr));
}
__device__ __forceinline__ void mma16816(float* d, const uint32_t* a, uint32_t b0, uint32_t b1) {
    asm volatile(
        "mma.sync.aligned.m16n8k16.row.col.f32.f16.f16.f32 "
        "{%0,%1,%2,%3}, {%4,%5,%6,%7}, {%8,%9}, {%0,%1,%2,%3};"
        : "+f"(d[0]), "+f"(d[1]), "+f"(d[2]), "+f"(d[3])
        : "r"(a[0]), "r"(a[1]), "r"(a[2]), "r"(a[3]), "r"(b0), "r"(b1));
}

__device__ __forceinline__ void load_tile(uint32_t smem_dst, const __half* __restrict__ src,
                                          int row0, int kk, int tid) {
#pragma unroll
    for (int i = 0; i < 4; i++) {
        int idx = tid + i * NTHR;
        int r  = idx >> 3;
        int cb = (idx & 7) << 4;
        uint32_t dst = smem_dst + r * 128 + (cb ^ ((r & 7) << 4));
        const void* s = (const char*)(src + (size_t)(row0 + r) * C + kk) + cb;
        asm volatile("cp.async.cg.shared.global [%0], [%1], 16;" :: "r"(dst), "l"(s));
    }
}

__global__ void __launch_bounds__(NTHR, 2) gemm_mma_kernel() {
    extern __shared__ char smem[];
    uint32_t sb = smem_u32(smem);
    int tid = threadIdx.x, lane = tid & 31, wid = tid >> 5;
    int z = blockIdx.z;
    int row0 = blockIdx.y * TM;
    int col0 = blockIdx.x * TN;

    const __half* Ah = g_Ah[z];
    const __half* Bh = g_Bh[z];

    auto load_chunk = [&](int ch, int stage) {
        int kk = ch * TK;
        uint32_t s = sb + stage * STAGE_BYTES;
        load_tile(s, Ah, row0, kk, tid);
        load_tile(s + STAGE_A, Bh, col0, kk, tid);
    };

    int wm = (wid >> 2) * 64;   // warp M offset
    int wn = (wid & 3) * 32;    // warp N offset

    float acc[4][4][4];
#pragma unroll
    for (int a = 0; a < 4; a++)
#pragma unroll
        for (int j = 0; j < 4; j++)
#pragma unroll
            for (int q = 0; q < 4; q++) acc[a][j][q] = 0.f;

    load_chunk(0, 0);
    asm volatile("cp.async.commit_group;");
    load_chunk(1, 1);
    asm volatile("cp.async.commit_group;");

    int arow = wm + (lane & 15);
    int acb  = (lane >> 4) << 4;
    int bg   = lane >> 3;
    int bn   = (bg >> 1) * 8 + (lane & 7);
    int bcb  = (bg & 1) << 4;

    int cur = 0, pre = 2;
    for (int ch = 0; ch < NCH; ch++) {
        asm volatile("cp.async.wait_group %0;" :: "n"(1));
        __syncthreads();
        if (ch + 2 < NCH) load_chunk(ch + 2, pre);
        asm volatile("cp.async.commit_group;");

        uint32_t smA = sb + cur * STAGE_BYTES;
        uint32_t smB = smA + STAGE_A;
#pragma unroll
        for (int ks = 0; ks < 4; ks++) {
            uint32_t a[4][4];
#pragma unroll
            for (int am = 0; am < 4; am++) {
                int row = arow + am * 16;
                uint32_t addr = smA + row * 128 + (((ks * 32) + acb) ^ ((row & 7) << 4));
                ldsm4(a[am], addr);
            }
#pragma unroll
            for (int p = 0; p < 2; p++) {
                int n = wn + p * 16 + bn;
                uint32_t addr = smB + n * 128 + (((ks * 32) + bcb) ^ ((n & 7) << 4));
                uint32_t b[4];
                ldsm4(b, addr);
#pragma unroll
                for (int am = 0; am < 4; am++) {
                    mma16816(acc[am][2 * p],     a[am], b[0], b[1]);
                    mma16816(acc[am][2 * p + 1], a[am], b[2], b[3]);
                }
            }
        }
        if (++cur == STAGES) cur = 0;
        if (++pre == STAGES) pre = 0;
    }

    // -------- epilogue: certain counts + ambiguous worklist --------
    __shared__ int s_n, s_base;
    __syncthreads();             // all smem reads of the last stage are done
    if (tid == 0) s_n = 0;
    __syncthreads();
    uint32_t* s_list = (uint32_t*)smem;   // reuse stage memory for the list

    const float* Dg = g_diag[z];
    int* cnt = g_cnt[z];
    uint32_t ztag = ((uint32_t)z) << 26;

    auto handle = [&](float v, float d, int row, int col, int& c) {
        if (col == row) return;
        if (v > d + THETA) {
            c++;
        } else if (v >= d - THETA) {
            int k = atomicAdd(&s_n, 1);
            if (k < LCAP) s_list[k] = ztag | ((uint32_t)row << 13) | (uint32_t)col;
        }
    };

#pragma unroll
    for (int am = 0; am < 4; am++) {
        int rlo = row0 + wm + am * 16 + (lane >> 2);
        int rhi = rlo + 8;
        float dlo = __ldg(&Dg[rlo]);
        float dhi = __ldg(&Dg[rhi]);
        int clo = 0, chi = 0;
#pragma unroll
        for (int j = 0; j < 4; j++) {
            int cb = col0 + wn + j * 8 + ((lane & 3) << 1);
            handle(acc[am][j][0], dlo, rlo, cb,     clo);
            handle(acc[am][j][1], dlo, rlo, cb + 1, clo);
            handle(acc[am][j][2], dhi, rhi, cb,     chi);
            handle(acc[am][j][3], dhi, rhi, cb + 1, chi);
        }
        clo += __shfl_xor_sync(0xffffffffu, clo, 1);
        clo += __shfl_xor_sync(0xffffffffu, clo, 2);
        chi += __shfl_xor_sync(0xffffffffu, chi, 1);
        chi += __shfl_xor_sync(0xffffffffu, chi, 2);
        if ((lane & 3) == 0) {
            atomicAdd(&cnt[rlo], clo);
            atomicAdd(&cnt[rhi], chi);
        }
    }

    // flush the per-CTA list with ONE global atomic
    __syncthreads();
    if (tid == 0) {
        int n = s_n < LCAP ? s_n : LCAP;
        s_base = atomicAdd(&g_nwork, n);
    }
    __syncthreads();
    int n = s_n < LCAP ? s_n : LCAP;
    for (int k = tid; k < n; k += NTHR) {
        int idx = s_base + k;
        if (idx < WCAP) g_work[idx] = s_list[k];
    }
}

// ---------------- kernel 3b: exact fp32 recheck of ambiguous pairs --------------
__global__ void recheck_kernel() {
    int nw = g_nwork;
    if (nw > WCAP) nw = WCAP;
    int gw     = (int)((blockIdx.x * blockDim.x + threadIdx.x) >> 5);
    int lane   = threadIdx.x & 31;
    int stride = (int)((gridDim.x * blockDim.x) >> 5);
    for (int w = gw; w < nw; w += stride) {
        uint32_t e = g_work[w];
        int z = (e >> 26) & 1;
        int i = (e >> 13) & 8191;
        int j = e & 8191;
        const float* a = g_Af[z] + (size_t)i * C;
        const float* b = g_Bf[z] + (size_t)j * C;
        float s = 0.f;
#pragma unroll
        for (int seg = 0; seg < 4; seg++) {
            float4 x = *(const float4*)(a + seg * 128 + lane * 4);
            float4 y = *(const float4*)(b + seg * 128 + lane * 4);
            s += x.x * y.x + x.y * y.y + x.z * y.z + x.w * y.w;
        }
#pragma unroll
        for (int m = 16; m; m >>= 1) s += __shfl_xor_sync(0xffffffffu, s, m);
        if (lane == 0 && s > g_diag[z][i]) atomicAdd(&g_cnt[z][i], 1);
    }
}

// ---------------- kernel 4: deterministic finalize ------------------------------
__global__ void finalize_kernel(float* __restrict__ out) {
    __shared__ float sm[16];
    int t = threadIdx.x;

    auto bsum = [&](float v) -> float {
#pragma unroll
        for (int m = 16; m; m >>= 1) v += __shfl_xor_sync(0xffffffffu, v, m);
        if ((t & 31) == 0) sm[t >> 5] = v;
        __syncthreads();
        float r = 0.f;
        if (t < 32) {
            r = (t < 16) ? sm[t] : 0.f;
#pragma unroll
            for (int m = 8; m; m >>= 1) r += __shfl_xor_sync(0xffffffffu, r, m);
        }
        __syncthreads();
        return r;
    };

    float s = 0.f;
    for (int i = t; i < N; i += 512) s += g_diag[0][i] + g_diag[1][i];
    float tot = bsum(s);
    if (t == 0) out[0] = -0.5f * tot / (float)N;

    for (int m = 0; m < 4; m++) {
        float S = 0.f, Q = 0.f;
#pragma unroll 8
        for (int ch = 0; ch < 64; ch++) {
            S += g_colsum[m][ch][t];
            Q += g_colsq[m][ch][t];
        }
        float var = (Q - S * S / (float)N) / (float)(N - 1);
        float sd = sqrtf(fmaxf(var, 0.f));
        float tots = bsum(sd);
        if (t == 0) out[1 + m] = tots / (float)C;
    }

    for (int z = 0; z < 2; z++) {
        const int* cnt = g_cnt[z];
        float c1 = 0.f, c5 = 0.f, c10 = 0.f, cm = 0.f;
        for (int i = t; i < N; i += 512) {
            int p = cnt[i];
            c1  += (p < 1)  ? 1.f : 0.f;
            c5  += (p < 5)  ? 1.f : 0.f;
            c10 += (p < 10) ? 1.f : 0.f;
            cm  += (float)p;
        }
        float t1 = bsum(c1);
        float t5 = bsum(c5);
        float t10 = bsum(c10);
        float tm = bsum(cm);
        if (t == 0) {
            out[5 + 4 * z + 0] = t1 / (float)N;
            out[5 + 4 * z + 1] = t5 / (float)N;
            out[5 + 4 * z + 2] = t10 / (float)N;
            out[5 + 4 * z + 3] = tm / (float)N;
        }
    }
}

// ---------------- launch ---------------------------------------------------------
extern "C" void kernel_launch(void* const* d_in, const int* in_sizes, int n_in,
                              void* d_out, int out_size) {
    const float* V  = (const float*)d_in[0];
    const float* T  = (const float*)d_in[1];
    const float* PV = (const float*)d_in[2];
    const float* PT = (const float*)d_in[3];

    cudaFuncSetAttribute(gemm_mma_kernel, cudaFuncAttributeMaxDynamicSharedMemorySize, SMEM_SIZE);

    zero_cnt_kernel<<<16, 512>>>();
    normalize_kernel<<<N, 128>>>(V, T, PV, PT);
    colstats_kernel<<<dim3(64, 4), 512>>>();
    gemm_mma_kernel<<<dim3(N / TN, N / TM, 2), NTHR, SMEM_SIZE>>>();
    recheck_kernel<<<1024, 256>>>();
    finalize_kernel<<<1, 512>>>((float*)d_out);
}

// round 11
// speedup vs baseline: 4.6660x; 1.0265x over previous
#include <cuda_runtime.h>
#include <cuda_fp16.h>
#include <cstdint>

#define N 8192
#define C 512
#define THETA 8e-5f
#define WCAP (1 << 22)      // global worklist capacity
#define LCAP 2048           // per-CTA smem worklist capacity (entries)

// ---------------- scratch (device globals; no allocation allowed) ----------------
// Problem z=0: A=Vn, B=PTn (s1).  z=1: A=Tn, B=PVn (s2).
__device__ __half g_Ah[2][N * C];     // fp16 normalized A (pass-1 GEMM)
__device__ __half g_Bh[2][N * C];     // fp16 normalized B
__device__ float  g_Af[2][N * C];     // fp32 normalized A (pass-2 exact dots)
__device__ float  g_Bf[2][N * C];     // fp32 normalized B
__device__ float  g_diag[2][N];       // exact fp32 diagonals
__device__ int    g_cnt[2][N];
__device__ int    g_nwork;
__device__ uint32_t g_work[WCAP];     // packed (z<<26)|(i<<13)|j
__device__ float g_colsum[4][64][C];
__device__ float g_colsq[4][64][C];

__device__ __forceinline__ uint32_t smem_u32(const void* p) {
    uint32_t a;
    asm("{ .reg .u64 t; cvta.to.shared.u64 t, %1; cvt.u32.u64 %0, t; }" : "=r"(a) : "l"(p));
    return a;
}

// ---------------- kernel 0: zero count accumulators (graph replays!) ------------
__global__ void zero_cnt_kernel() {
    int i = blockIdx.x * blockDim.x + threadIdx.x;
    if (i < N) { g_cnt[0][i] = 0; g_cnt[1][i] = 0; }
    if (i == 0) g_nwork = 0;
}

__device__ __forceinline__ float dot4(float4 a, float4 b) {
    return a.x * b.x + a.y * b.y + a.z * b.z + a.w * b.w;
}

__device__ __forceinline__ void store_nf(__half* h, float* f, size_t base, float4 y, float r) {
    float4 o = make_float4(y.x * r, y.y * r, y.z * r, y.w * r);
    *(float4*)(f + base) = o;
    *(__half2*)(h + base)     = __floats2half2_rn(o.x, o.y);
    *(__half2*)(h + base + 2) = __floats2half2_rn(o.z, o.w);
}

// ---------------- kernel 1: normalize -> fp16 + fp32 copies + exact diagonals ---
__global__ void normalize_kernel(const float* __restrict__ V, const float* __restrict__ T,
                                 const float* __restrict__ PV, const float* __restrict__ PT) {
    int row = blockIdx.x;
    int t   = threadIdx.x;
    size_t base = (size_t)row * C + 4 * t;

    float4 v  = *(const float4*)(V  + base);
    float4 tf = *(const float4*)(T  + base);
    float4 pv = *(const float4*)(PV + base);
    float4 pt = *(const float4*)(PT + base);

    float p0 = dot4(v, v),  p1 = dot4(tf, tf), p2 = dot4(pv, pv);
    float p3 = dot4(pt, pt), p4 = dot4(v, pt), p5 = dot4(tf, pv);

#pragma unroll
    for (int m = 16; m; m >>= 1) {
        p0 += __shfl_xor_sync(0xffffffffu, p0, m);
        p1 += __shfl_xor_sync(0xffffffffu, p1, m);
        p2 += __shfl_xor_sync(0xffffffffu, p2, m);
        p3 += __shfl_xor_sync(0xffffffffu, p3, m);
        p4 += __shfl_xor_sync(0xffffffffu, p4, m);
        p5 += __shfl_xor_sync(0xffffffffu, p5, m);
    }
    __shared__ float sm[4][6];
    int w = t >> 5;
    if ((t & 31) == 0) {
        sm[w][0] = p0; sm[w][1] = p1; sm[w][2] = p2;
        sm[w][3] = p3; sm[w][4] = p4; sm[w][5] = p5;
    }
    __syncthreads();
    float s0 = sm[0][0] + sm[1][0] + sm[2][0] + sm[3][0];
    float s1 = sm[0][1] + sm[1][1] + sm[2][1] + sm[3][1];
    float s2 = sm[0][2] + sm[1][2] + sm[2][2] + sm[3][2];
    float s3 = sm[0][3] + sm[1][3] + sm[2][3] + sm[3][3];
    float s4 = sm[0][4] + sm[1][4] + sm[2][4] + sm[3][4];
    float s5 = sm[0][5] + sm[1][5] + sm[2][5] + sm[3][5];

    float rv  = rsqrtf(s0);
    float rt_ = rsqrtf(s1);
    float rpv = rsqrtf(s2);
    float rpt = rsqrtf(s3);

    store_nf(g_Ah[0], g_Af[0], base, v,  rv);   // Vn  (A of problem 0)
    store_nf(g_Ah[1], g_Af[1], base, tf, rt_);  // Tn  (A of problem 1)
    store_nf(g_Bh[1], g_Bf[1], base, pv, rpv);  // PVn (B of problem 1)
    store_nf(g_Bh[0], g_Bf[0], base, pt, rpt);  // PTn (B of problem 0)

    if (t == 0) {
        g_diag[0][row] = s4 * rv  * rpt;  // v_n . p_t_n
        g_diag[1][row] = s5 * rt_ * rpv;  // t_n . p_v_n
    }
}

// ---------------- kernel 2: per-column partial sums for std (fp32 copies) -------
__global__ void colstats_kernel() {
    int mat = blockIdx.y, chunk = blockIdx.x, col = threadIdx.x;
    const float* M;
    switch (mat) {
        case 0: M = g_Af[0]; break;  // v_feat
        case 1: M = g_Af[1]; break;  // t_feat
        case 2: M = g_Bf[1]; break;  // p_v
        default: M = g_Bf[0]; break; // p_t
    }
    float s = 0.f, q = 0.f;
    int r0 = chunk * 128;
#pragma unroll 4
    for (int r = r0; r < r0 + 128; r++) {
        float x = M[(size_t)r * C + col];
        s += x;
        q += x * x;
    }
    g_colsum[mat][chunk][col] = s;
    g_colsq[mat][chunk][col]  = q;
}

// ---------------- kernel 3: fp16 warp-MMA GEMM + threshold-count epilogue -------
// Each CTA: one 128-row tile x FOUR 128-col tiles, as ONE continuous 32-chunk
// pipeline (tile-major chunk stream; acc dumped+zeroed every 8 chunks while the
// next tile's loads are in flight). 3-stage ring, 256 thr, 8 warps (64x32),
// 2 CTAs/SM. Dedicated smem worklist (stages stay live across epilogues).
#define TM 128
#define TN 128
#define TK 64
#define JT 4                              // column tiles per CTA
#define STAGES 3
#define NTHR 256
#define STAGE_A (TM * 128)
#define STAGE_B (TN * 128)
#define STAGE_BYTES (STAGE_A + STAGE_B)   // 32768
#define WLIST_OFF (STAGES * STAGE_BYTES)  // 98304
#define SMEM_SIZE (WLIST_OFF + LCAP * 4)  // 106496
#define NCHT (JT * 8)                     // 32 chunks total

__device__ __forceinline__ void ldsm4(uint32_t* r, uint32_t addr) {
    asm volatile("ldmatrix.sync.aligned.m8n8.x4.shared.b16 {%0,%1,%2,%3}, [%4];"
                 : "=r"(r[0]), "=r"(r[1]), "=r"(r[2]), "=r"(r[3]) : "r"(addr));
}
__device__ __forceinline__ void mma16816(float* d, const uint32_t* a, uint32_t b0, uint32_t b1) {
    asm volatile(
        "mma.sync.aligned.m16n8k16.row.col.f32.f16.f16.f32 "
        "{%0,%1,%2,%3}, {%4,%5,%6,%7}, {%8,%9}, {%0,%1,%2,%3};"
        : "+f"(d[0]), "+f"(d[1]), "+f"(d[2]), "+f"(d[3])
        : "r"(a[0]), "r"(a[1]), "r"(a[2]), "r"(a[3]), "r"(b0), "r"(b1));
}

__device__ __forceinline__ void load_tile(uint32_t smem_dst, const __half* __restrict__ src,
                                          int row0, int kk, int tid) {
#pragma unroll
    for (int i = 0; i < 4; i++) {
        int idx = tid + i * NTHR;
        int r  = idx >> 3;
        int cb = (idx & 7) << 4;
        uint32_t dst = smem_dst + r * 128 + (cb ^ ((r & 7) << 4));
        const void* s = (const char*)(src + (size_t)(row0 + r) * C + kk) + cb;
        asm volatile("cp.async.cg.shared.global [%0], [%1], 16;" :: "r"(dst), "l"(s));
    }
}

__global__ void __launch_bounds__(NTHR, 2) gemm_mma_kernel() {
    extern __shared__ char smem[];
    uint32_t sb = smem_u32(smem);
    int tid = threadIdx.x, lane = tid & 31, wid = tid >> 5;
    int z = blockIdx.z;
    int row0 = blockIdx.y * TM;
    int col_base = blockIdx.x * (TN * JT);

    const __half* Ah = g_Ah[z];
    const __half* Bh = g_Bh[z];

    __shared__ int s_n, s_base;
    uint32_t* s_list = (uint32_t*)(smem + WLIST_OFF);
    if (tid == 0) s_n = 0;

    auto load_chunk = [&](int t, int stage) {
        int kk = (t & 7) * TK;
        int jc = col_base + (t >> 3) * TN;
        uint32_t s = sb + stage * STAGE_BYTES;
        load_tile(s, Ah, row0, kk, tid);
        load_tile(s + STAGE_A, Bh, jc, kk, tid);
    };

    int wm = (wid >> 2) * 64;   // warp M offset
    int wn = (wid & 3) * 32;    // warp N offset

    float acc[4][4][4];
#pragma unroll
    for (int a = 0; a < 4; a++)
#pragma unroll
        for (int j = 0; j < 4; j++)
#pragma unroll
            for (int q = 0; q < 4; q++) acc[a][j][q] = 0.f;

    load_chunk(0, 0);
    asm volatile("cp.async.commit_group;");
    load_chunk(1, 1);
    asm volatile("cp.async.commit_group;");

    int arow = wm + (lane & 15);
    int acb  = (lane >> 4) << 4;
    int bg   = lane >> 3;
    int bn   = (bg >> 1) * 8 + (lane & 7);
    int bcb  = (bg & 1) << 4;

    const float* Dg = g_diag[z];
    int* cnt = g_cnt[z];
    uint32_t ztag = ((uint32_t)z) << 26;

    auto handle = [&](float v, float d, int row, int col, int& c) {
        if (col == row) return;
        if (v > d + THETA) {
            c++;
        } else if (v >= d - THETA) {
            int k = atomicAdd(&s_n, 1);
            if (k < LCAP) s_list[k] = ztag | ((uint32_t)row << 13) | (uint32_t)col;
        }
    };

    int cur = 0, pre = 2;
    for (int t = 0; t < NCHT; t++) {
        asm volatile("cp.async.wait_group %0;" :: "n"(1));
        __syncthreads();
        if (t + 2 < NCHT) load_chunk(t + 2, pre);
        asm volatile("cp.async.commit_group;");

        uint32_t smA = sb + cur * STAGE_BYTES;
        uint32_t smB = smA + STAGE_A;
#pragma unroll
        for (int ks = 0; ks < 4; ks++) {
            uint32_t a[4][4];
#pragma unroll
            for (int am = 0; am < 4; am++) {
                int row = arow + am * 16;
                uint32_t addr = smA + row * 128 + (((ks * 32) + acb) ^ ((row & 7) << 4));
                ldsm4(a[am], addr);
            }
#pragma unroll
            for (int p = 0; p < 2; p++) {
                int n = wn + p * 16 + bn;
                uint32_t addr = smB + n * 128 + (((ks * 32) + bcb) ^ ((n & 7) << 4));
                uint32_t b[4];
                ldsm4(b, addr);
#pragma unroll
                for (int am = 0; am < 4; am++) {
                    mma16816(acc[am][2 * p],     a[am], b[0], b[1]);
                    mma16816(acc[am][2 * p + 1], a[am], b[2], b[3]);
                }
            }
        }
        if (++cur == STAGES) cur = 0;
        if (++pre == STAGES) pre = 0;

        if ((t & 7) == 7) {
            // -------- per-tile epilogue (prefetches for next tile stay in flight)
            int col0 = col_base + (t >> 3) * TN;
#pragma unroll
            for (int am = 0; am < 4; am++) {
                int rlo = row0 + wm + am * 16 + (lane >> 2);
                int rhi = rlo + 8;
                float dlo = __ldg(&Dg[rlo]);
                float dhi = __ldg(&Dg[rhi]);
                int clo = 0, chi = 0;
#pragma unroll
                for (int j = 0; j < 4; j++) {
                    int cb = col0 + wn + j * 8 + ((lane & 3) << 1);
                    handle(acc[am][j][0], dlo, rlo, cb,     clo);
                    handle(acc[am][j][1], dlo, rlo, cb + 1, clo);
                    handle(acc[am][j][2], dhi, rhi, cb,     chi);
                    handle(acc[am][j][3], dhi, rhi, cb + 1, chi);
                }
                clo += __shfl_xor_sync(0xffffffffu, clo, 1);
                clo += __shfl_xor_sync(0xffffffffu, clo, 2);
                chi += __shfl_xor_sync(0xffffffffu, chi, 1);
                chi += __shfl_xor_sync(0xffffffffu, chi, 2);
                if ((lane & 3) == 0) {
                    atomicAdd(&cnt[rlo], clo);
                    atomicAdd(&cnt[rhi], chi);
                }
#pragma unroll
                for (int j = 0; j < 4; j++)
#pragma unroll
                    for (int q = 0; q < 4; q++) acc[am][j][q] = 0.f;
            }
        }
    }

    // flush the per-CTA worklist with ONE global atomic
    __syncthreads();
    if (tid == 0) {
        int n = s_n < LCAP ? s_n : LCAP;
        s_base = atomicAdd(&g_nwork, n);
    }
    __syncthreads();
    int n = s_n < LCAP ? s_n : LCAP;
    for (int k = tid; k < n; k += NTHR) {
        int idx = s_base + k;
        if (idx < WCAP) g_work[idx] = s_list[k];
    }
}

// ---------------- kernel 3b: exact fp32 recheck of ambiguous pairs --------------
__global__ void recheck_kernel() {
    int nw = g_nwork;
    if (nw > WCAP) nw = WCAP;
    int gw     = (int)((blockIdx.x * blockDim.x + threadIdx.x) >> 5);
    int lane   = threadIdx.x & 31;
    int stride = (int)((gridDim.x * blockDim.x) >> 5);
    for (int w = gw; w < nw; w += stride) {
        uint32_t e = g_work[w];
        int z = (e >> 26) & 1;
        int i = (e >> 13) & 8191;
        int j = e & 8191;
        const float* a = g_Af[z] + (size_t)i * C;
        const float* b = g_Bf[z] + (size_t)j * C;
        float s = 0.f;
#pragma unroll
        for (int seg = 0; seg < 4; seg++) {
            float4 x = *(const float4*)(a + seg * 128 + lane * 4);
            float4 y = *(const float4*)(b + seg * 128 + lane * 4);
            s += x.x * y.x + x.y * y.y + x.z * y.z + x.w * y.w;
        }
#pragma unroll
        for (int m = 16; m; m >>= 1) s += __shfl_xor_sync(0xffffffffu, s, m);
        if (lane == 0 && s > g_diag[z][i]) atomicAdd(&g_cnt[z][i], 1);
    }
}

// ---------------- kernel 4: deterministic finalize ------------------------------
__global__ void finalize_kernel(float* __restrict__ out) {
    __shared__ float sm[16];
    int t = threadIdx.x;

    auto bsum = [&](float v) -> float {
#pragma unroll
        for (int m = 16; m; m >>= 1) v += __shfl_xor_sync(0xffffffffu, v, m);
        if ((t & 31) == 0) sm[t >> 5] = v;
        __syncthreads();
        float r = 0.f;
        if (t < 32) {
            r = (t < 16) ? sm[t] : 0.f;
#pragma unroll
            for (int m = 8; m; m >>= 1) r += __shfl_xor_sync(0xffffffffu, r, m);
        }
        __syncthreads();
        return r;
    };

    float s = 0.f;
    for (int i = t; i < N; i += 512) s += g_diag[0][i] + g_diag[1][i];
    float tot = bsum(s);
    if (t == 0) out[0] = -0.5f * tot / (float)N;

    for (int m = 0; m < 4; m++) {
        float S = 0.f, Q = 0.f;
#pragma unroll 8
        for (int ch = 0; ch < 64; ch++) {
            S += g_colsum[m][ch][t];
            Q += g_colsq[m][ch][t];
        }
        float var = (Q - S * S / (float)N) / (float)(N - 1);
        float sd = sqrtf(fmaxf(var, 0.f));
        float tots = bsum(sd);
        if (t == 0) out[1 + m] = tots / (float)C;
    }

    for (int z = 0; z < 2; z++) {
        const int* cnt = g_cnt[z];
        float c1 = 0.f, c5 = 0.f, c10 = 0.f, cm = 0.f;
        for (int i = t; i < N; i += 512) {
            int p = cnt[i];
            c1  += (p < 1)  ? 1.f : 0.f;
            c5  += (p < 5)  ? 1.f : 0.f;
            c10 += (p < 10) ? 1.f : 0.f;
            cm  += (float)p;
        }
        float t1 = bsum(c1);
        float t5 = bsum(c5);
        float t10 = bsum(c10);
        float tm = bsum(cm);
        if (t == 0) {
            out[5 + 4 * z + 0] = t1 / (float)N;
            out[5 + 4 * z + 1] = t5 / (float)N;
            out[5 + 4 * z + 2] = t10 / (float)N;
            out[5 + 4 * z + 3] = tm / (float)N;
        }
    }
}

// ---------------- launch ---------------------------------------------------------
extern "C" void kernel_launch(void* const* d_in, const int* in_sizes, int n_in,
                              void* d_out, int out_size) {
    const float* V  = (const float*)d_in[0];
    const float* T  = (const float*)d_in[1];
    const float* PV = (const float*)d_in[2];
    const float* PT = (const float*)d_in[3];

    cudaFuncSetAttribute(gemm_mma_kernel, cudaFuncAttributeMaxDynamicSharedMemorySize, SMEM_SIZE);

    zero_cnt_kernel<<<16, 512>>>();
    normalize_kernel<<<N, 128>>>(V, T, PV, PT);
    colstats_kernel<<<dim3(64, 4), 512>>>();
    gemm_mma_kernel<<<dim3(N / (TN * JT), N / TM, 2), NTHR, SMEM_SIZE>>>();
    recheck_kernel<<<1024, 256>>>();
    finalize_kernel<<<1, 512>>>((float*)d_out);
}

// round 12
// speedup vs baseline: 5.0571x; 1.0838x over previous
#include <cuda_runtime.h>
#include <cuda_fp16.h>
#include <cstdint>

#define N 8192
#define C 512
#define THETA 8e-5f
#define WCAP (1 << 22)      // global worklist capacity
#define LCAP 2048           // per-CTA smem worklist capacity (entries)

// ---------------- scratch (device globals; no allocation allowed) ----------------
// Problem z=0: A=Vn, B=PTn (s1).  z=1: A=Tn, B=PVn (s2).
__device__ __half g_Ah[2][N * C];     // fp16 normalized A (pass-1 GEMM)
__device__ __half g_Bh[2][N * C];     // fp16 normalized B
__device__ float  g_Af[2][N * C];     // fp32 normalized A (pass-2 exact dots)
__device__ float  g_Bf[2][N * C];     // fp32 normalized B
__device__ float  g_diag[2][N];       // exact fp32 diagonals
__device__ int    g_cnt[2][N];
__device__ int    g_nwork;
__device__ uint32_t g_work[WCAP];     // packed (z<<26)|(i<<13)|j
__device__ float g_colsum[4][64][C];
__device__ float g_colsq[4][64][C];

__device__ __forceinline__ uint32_t smem_u32(const void* p) {
    uint32_t a;
    asm("{ .reg .u64 t; cvta.to.shared.u64 t, %1; cvt.u32.u64 %0, t; }" : "=r"(a) : "l"(p));
    return a;
}

// ---------------- kernel 0: zero count accumulators (graph replays!) ------------
__global__ void zero_cnt_kernel() {
    int i = blockIdx.x * blockDim.x + threadIdx.x;
    if (i < N) { g_cnt[0][i] = 0; g_cnt[1][i] = 0; }
    if (i == 0) g_nwork = 0;
}

__device__ __forceinline__ float dot4(float4 a, float4 b) {
    return a.x * b.x + a.y * b.y + a.z * b.z + a.w * b.w;
}

__device__ __forceinline__ void store_nf(__half* h, float* f, size_t base, float4 y, float r) {
    float4 o = make_float4(y.x * r, y.y * r, y.z * r, y.w * r);
    *(float4*)(f + base) = o;
    *(__half2*)(h + base)     = __floats2half2_rn(o.x, o.y);
    *(__half2*)(h + base + 2) = __floats2half2_rn(o.z, o.w);
}

// ---------------- kernel 1: normalize -> fp16 + fp32 copies + exact diagonals ---
__global__ void normalize_kernel(const float* __restrict__ V, const float* __restrict__ T,
                                 const float* __restrict__ PV, const float* __restrict__ PT) {
    int row = blockIdx.x;
    int t   = threadIdx.x;
    size_t base = (size_t)row * C + 4 * t;

    float4 v  = *(const float4*)(V  + base);
    float4 tf = *(const float4*)(T  + base);
    float4 pv = *(const float4*)(PV + base);
    float4 pt = *(const float4*)(PT + base);

    float p0 = dot4(v, v),  p1 = dot4(tf, tf), p2 = dot4(pv, pv);
    float p3 = dot4(pt, pt), p4 = dot4(v, pt), p5 = dot4(tf, pv);

#pragma unroll
    for (int m = 16; m; m >>= 1) {
        p0 += __shfl_xor_sync(0xffffffffu, p0, m);
        p1 += __shfl_xor_sync(0xffffffffu, p1, m);
        p2 += __shfl_xor_sync(0xffffffffu, p2, m);
        p3 += __shfl_xor_sync(0xffffffffu, p3, m);
        p4 += __shfl_xor_sync(0xffffffffu, p4, m);
        p5 += __shfl_xor_sync(0xffffffffu, p5, m);
    }
    __shared__ float sm[4][6];
    int w = t >> 5;
    if ((t & 31) == 0) {
        sm[w][0] = p0; sm[w][1] = p1; sm[w][2] = p2;
        sm[w][3] = p3; sm[w][4] = p4; sm[w][5] = p5;
    }
    __syncthreads();
    float s0 = sm[0][0] + sm[1][0] + sm[2][0] + sm[3][0];
    float s1 = sm[0][1] + sm[1][1] + sm[2][1] + sm[3][1];
    float s2 = sm[0][2] + sm[1][2] + sm[2][2] + sm[3][2];
    float s3 = sm[0][3] + sm[1][3] + sm[2][3] + sm[3][3];
    float s4 = sm[0][4] + sm[1][4] + sm[2][4] + sm[3][4];
    float s5 = sm[0][5] + sm[1][5] + sm[2][5] + sm[3][5];

    float rv  = rsqrtf(s0);
    float rt_ = rsqrtf(s1);
    float rpv = rsqrtf(s2);
    float rpt = rsqrtf(s3);

    store_nf(g_Ah[0], g_Af[0], base, v,  rv);   // Vn  (A of problem 0)
    store_nf(g_Ah[1], g_Af[1], base, tf, rt_);  // Tn  (A of problem 1)
    store_nf(g_Bh[1], g_Bf[1], base, pv, rpv);  // PVn (B of problem 1)
    store_nf(g_Bh[0], g_Bf[0], base, pt, rpt);  // PTn (B of problem 0)

    if (t == 0) {
        g_diag[0][row] = s4 * rv  * rpt;  // v_n . p_t_n
        g_diag[1][row] = s5 * rt_ * rpv;  // t_n . p_v_n
    }
}

// ---------------- kernel 2: per-column partial sums for std (fp32 copies) -------
__global__ void colstats_kernel() {
    int mat = blockIdx.y, chunk = blockIdx.x, col = threadIdx.x;
    const float* M;
    switch (mat) {
        case 0: M = g_Af[0]; break;  // v_feat
        case 1: M = g_Af[1]; break;  // t_feat
        case 2: M = g_Bf[1]; break;  // p_v
        default: M = g_Bf[0]; break; // p_t
    }
    float s = 0.f, q = 0.f;
    int r0 = chunk * 128;
#pragma unroll 4
    for (int r = r0; r < r0 + 128; r++) {
        float x = M[(size_t)r * C + col];
        s += x;
        q += x * x;
    }
    g_colsum[mat][chunk][col] = s;
    g_colsq[mat][chunk][col]  = q;
}

// ---------------- kernel 3: fp16 warp-MMA GEMM + branchless count epilogue ------
// Each CTA: one 128-row tile x FOUR 128-col tiles as one continuous 32-chunk
// pipeline. Per-tile epilogue is branchless: count += (v > d+THETA); band
// membership packed into a 64-bit per-thread mask, decoded in a rare slow path.
// Counts accumulate in registers across tiles; one shfl+atomic set per kernel.
#define TM 128
#define TN 128
#define TK 64
#define JT 4                              // column tiles per CTA
#define STAGES 3
#define NTHR 256
#define STAGE_A (TM * 128)
#define STAGE_B (TN * 128)
#define STAGE_BYTES (STAGE_A + STAGE_B)   // 32768
#define WLIST_OFF (STAGES * STAGE_BYTES)  // 98304
#define SMEM_SIZE (WLIST_OFF + LCAP * 4)  // 106496
#define NCHT (JT * 8)                     // 32 chunks total

__device__ __forceinline__ void ldsm4(uint32_t* r, uint32_t addr) {
    asm volatile("ldmatrix.sync.aligned.m8n8.x4.shared.b16 {%0,%1,%2,%3}, [%4];"
                 : "=r"(r[0]), "=r"(r[1]), "=r"(r[2]), "=r"(r[3]) : "r"(addr));
}
__device__ __forceinline__ void mma16816(float* d, const uint32_t* a, uint32_t b0, uint32_t b1) {
    asm volatile(
        "mma.sync.aligned.m16n8k16.row.col.f32.f16.f16.f32 "
        "{%0,%1,%2,%3}, {%4,%5,%6,%7}, {%8,%9}, {%0,%1,%2,%3};"
        : "+f"(d[0]), "+f"(d[1]), "+f"(d[2]), "+f"(d[3])
        : "r"(a[0]), "r"(a[1]), "r"(a[2]), "r"(a[3]), "r"(b0), "r"(b1));
}

__device__ __forceinline__ void load_tile(uint32_t smem_dst, const __half* __restrict__ src,
                                          int row0, int kk, int tid) {
#pragma unroll
    for (int i = 0; i < 4; i++) {
        int idx = tid + i * NTHR;
        int r  = idx >> 3;
        int cb = (idx & 7) << 4;
        uint32_t dst = smem_dst + r * 128 + (cb ^ ((r & 7) << 4));
        const void* s = (const char*)(src + (size_t)(row0 + r) * C + kk) + cb;
        asm volatile("cp.async.cg.shared.global [%0], [%1], 16;" :: "r"(dst), "l"(s));
    }
}

__global__ void __launch_bounds__(NTHR, 2) gemm_mma_kernel() {
    extern __shared__ char smem[];
    uint32_t sb = smem_u32(smem);
    int tid = threadIdx.x, lane = tid & 31, wid = tid >> 5;
    int z = blockIdx.z;
    int row0 = blockIdx.y * TM;
    int col_base = blockIdx.x * (TN * JT);

    const __half* Ah = g_Ah[z];
    const __half* Bh = g_Bh[z];

    __shared__ int s_n, s_base;
    uint32_t* s_list = (uint32_t*)(smem + WLIST_OFF);
    if (tid == 0) s_n = 0;

    auto load_chunk = [&](int t, int stage) {
        int kk = (t & 7) * TK;
        int jc = col_base + (t >> 3) * TN;
        uint32_t s = sb + stage * STAGE_BYTES;
        load_tile(s, Ah, row0, kk, tid);
        load_tile(s + STAGE_A, Bh, jc, kk, tid);
    };

    int wm = (wid >> 2) * 64;   // warp M offset
    int wn = (wid & 3) * 32;    // warp N offset

    float acc[4][4][4];
#pragma unroll
    for (int a = 0; a < 4; a++)
#pragma unroll
        for (int j = 0; j < 4; j++)
#pragma unroll
            for (int q = 0; q < 4; q++) acc[a][j][q] = 0.f;

    int cnt_lo[4] = {0, 0, 0, 0};   // counts for rows rlo(am), across all tiles
    int cnt_hi[4] = {0, 0, 0, 0};   // counts for rows rhi(am)

    load_chunk(0, 0);
    asm volatile("cp.async.commit_group;");
    load_chunk(1, 1);
    asm volatile("cp.async.commit_group;");

    int arow = wm + (lane & 15);
    int acb  = (lane >> 4) << 4;
    int bg   = lane >> 3;
    int bn   = (bg >> 1) * 8 + (lane & 7);
    int bcb  = (bg & 1) << 4;

    const float* Dg = g_diag[z];
    int* cnt = g_cnt[z];
    uint32_t ztag = ((uint32_t)z) << 26;

    int cur = 0, pre = 2;
    for (int t = 0; t < NCHT; t++) {
        asm volatile("cp.async.wait_group %0;" :: "n"(1));
        __syncthreads();
        if (t + 2 < NCHT) load_chunk(t + 2, pre);
        asm volatile("cp.async.commit_group;");

        uint32_t smA = sb + cur * STAGE_BYTES;
        uint32_t smB = smA + STAGE_A;
#pragma unroll
        for (int ks = 0; ks < 4; ks++) {
            uint32_t a[4][4];
#pragma unroll
            for (int am = 0; am < 4; am++) {
                int row = arow + am * 16;
                uint32_t addr = smA + row * 128 + (((ks * 32) + acb) ^ ((row & 7) << 4));
                ldsm4(a[am], addr);
            }
#pragma unroll
            for (int p = 0; p < 2; p++) {
                int n = wn + p * 16 + bn;
                uint32_t addr = smB + n * 128 + (((ks * 32) + bcb) ^ ((n & 7) << 4));
                uint32_t b[4];
                ldsm4(b, addr);
#pragma unroll
                for (int am = 0; am < 4; am++) {
                    mma16816(acc[am][2 * p],     a[am], b[0], b[1]);
                    mma16816(acc[am][2 * p + 1], a[am], b[2], b[3]);
                }
            }
        }
        if (++cur == STAGES) cur = 0;
        if (++pre == STAGES) pre = 0;

        if ((t & 7) == 7) {
            // -------- branchless per-tile epilogue --------
            int col0 = col_base + (t >> 3) * TN;
            uint32_t bm0 = 0, bm1 = 0;   // 64-bit band mask; bit = am*16 + j*4 + q
#pragma unroll
            for (int am = 0; am < 4; am++) {
                int rlo = row0 + wm + am * 16 + (lane >> 2);
                float dl = __ldg(&Dg[rlo]);
                float dh = __ldg(&Dg[rlo + 8]);
                float dlp = dl + THETA, dlm = dl - THETA;
                float dhp = dh + THETA, dhm = dh - THETA;
                int clo = 0, chi = 0;
#pragma unroll
                for (int j = 0; j < 4; j++) {
                    float v0 = acc[am][j][0], v1 = acc[am][j][1];
                    float v2 = acc[am][j][2], v3 = acc[am][j][3];
                    bool g0 = v0 > dlp, g1 = v1 > dlp;
                    bool g2 = v2 > dhp, g3 = v3 > dhp;
                    clo += (int)g0 + (int)g1;
                    chi += (int)g2 + (int)g3;
                    uint32_t b = (uint32_t)((v0 > dlm) != g0)
                               | ((uint32_t)((v1 > dlm) != g1) << 1)
                               | ((uint32_t)((v2 > dhm) != g2) << 2)
                               | ((uint32_t)((v3 > dhm) != g3) << 3);
                    int sh = am * 16 + j * 4;
                    if (am < 2) bm0 |= b << sh;
                    else        bm1 |= b << (sh - 32);
                    acc[am][j][0] = acc[am][j][1] = acc[am][j][2] = acc[am][j][3] = 0.f;
                }
                cnt_lo[am] += clo;
                cnt_hi[am] += chi;
            }
            if (bm0 | bm1) {
                // rare slow path: decode band bits -> worklist
#pragma unroll
                for (int half = 0; half < 2; half++) {
                    uint32_t m = half ? bm1 : bm0;
                    while (m) {
                        int b = __ffs(m) - 1;
                        m &= m - 1;
                        int bit = half * 32 + b;
                        int am = bit >> 4, j = (bit >> 2) & 3, q = bit & 3;
                        int row = row0 + wm + am * 16 + (lane >> 2) + ((q >> 1) << 3);
                        int col = col0 + wn + j * 8 + ((lane & 3) << 1) + (q & 1);
                        int k = atomicAdd(&s_n, 1);
                        if (k < LCAP) s_list[k] = ztag | ((uint32_t)row << 13) | (uint32_t)col;
                    }
                }
            }
        }
    }

    // -------- final count reduction: once per kernel --------
#pragma unroll
    for (int am = 0; am < 4; am++) {
        int rlo = row0 + wm + am * 16 + (lane >> 2);
        int clo = cnt_lo[am], chi = cnt_hi[am];
        clo += __shfl_xor_sync(0xffffffffu, clo, 1);
        clo += __shfl_xor_sync(0xffffffffu, clo, 2);
        chi += __shfl_xor_sync(0xffffffffu, chi, 1);
        chi += __shfl_xor_sync(0xffffffffu, chi, 2);
        if ((lane & 3) == 0) {
            atomicAdd(&cnt[rlo], clo);
            atomicAdd(&cnt[rlo + 8], chi);
        }
    }

    // flush the per-CTA worklist with ONE global atomic
    __syncthreads();
    if (tid == 0) {
        int n = s_n < LCAP ? s_n : LCAP;
        s_base = atomicAdd(&g_nwork, n);
    }
    __syncthreads();
    int n = s_n < LCAP ? s_n : LCAP;
    for (int k = tid; k < n; k += NTHR) {
        int idx = s_base + k;
        if (idx < WCAP) g_work[idx] = s_list[k];
    }
}

// ---------------- kernel 3b: exact fp32 recheck of ambiguous pairs --------------
__global__ void recheck_kernel() {
    int nw = g_nwork;
    if (nw > WCAP) nw = WCAP;
    int gw     = (int)((blockIdx.x * blockDim.x + threadIdx.x) >> 5);
    int lane   = threadIdx.x & 31;
    int stride = (int)((gridDim.x * blockDim.x) >> 5);
    for (int w = gw; w < nw; w += stride) {
        uint32_t e = g_work[w];
        int z = (e >> 26) & 1;
        int i = (e >> 13) & 8191;
        int j = e & 8191;
        if (i == j) continue;   // diagonal: never counts
        const float* a = g_Af[z] + (size_t)i * C;
        const float* b = g_Bf[z] + (size_t)j * C;
        float s = 0.f;
#pragma unroll
        for (int seg = 0; seg < 4; seg++) {
            float4 x = *(const float4*)(a + seg * 128 + lane * 4);
            float4 y = *(const float4*)(b + seg * 128 + lane * 4);
            s += x.x * y.x + x.y * y.y + x.z * y.z + x.w * y.w;
        }
#pragma unroll
        for (int m = 16; m; m >>= 1) s += __shfl_xor_sync(0xffffffffu, s, m);
        if (lane == 0 && s > g_diag[z][i]) atomicAdd(&g_cnt[z][i], 1);
    }
}

// ---------------- kernel 4: deterministic finalize ------------------------------
__global__ void finalize_kernel(float* __restrict__ out) {
    __shared__ float sm[16];
    int t = threadIdx.x;

    auto bsum = [&](float v) -> float {
#pragma unroll
        for (int m = 16; m; m >>= 1) v += __shfl_xor_sync(0xffffffffu, v, m);
        if ((t & 31) == 0) sm[t >> 5] = v;
        __syncthreads();
        float r = 0.f;
        if (t < 32) {
            r = (t < 16) ? sm[t] : 0.f;
#pragma unroll
            for (int m = 8; m; m >>= 1) r += __shfl_xor_sync(0xffffffffu, r, m);
        }
        __syncthreads();
        return r;
    };

    float s = 0.f;
    for (int i = t; i < N; i += 512) s += g_diag[0][i] + g_diag[1][i];
    float tot = bsum(s);
    if (t == 0) out[0] = -0.5f * tot / (float)N;

    for (int m = 0; m < 4; m++) {
        float S = 0.f, Q = 0.f;
#pragma unroll 8
        for (int ch = 0; ch < 64; ch++) {
            S += g_colsum[m][ch][t];
            Q += g_colsq[m][ch][t];
        }
        float var = (Q - S * S / (float)N) / (float)(N - 1);
        float sd = sqrtf(fmaxf(var, 0.f));
        float tots = bsum(sd);
        if (t == 0) out[1 + m] = tots / (float)C;
    }

    for (int z = 0; z < 2; z++) {
        const int* cnt = g_cnt[z];
        float c1 = 0.f, c5 = 0.f, c10 = 0.f, cm = 0.f;
        for (int i = t; i < N; i += 512) {
            int p = cnt[i];
            c1  += (p < 1)  ? 1.f : 0.f;
            c5  += (p < 5)  ? 1.f : 0.f;
            c10 += (p < 10) ? 1.f : 0.f;
            cm  += (float)p;
        }
        float t1 = bsum(c1);
        float t5 = bsum(c5);
        float t10 = bsum(c10);
        float tm = bsum(cm);
        if (t == 0) {
            out[5 + 4 * z + 0] = t1 / (float)N;
            out[5 + 4 * z + 1] = t5 / (float)N;
            out[5 + 4 * z + 2] = t10 / (float)N;
            out[5 + 4 * z + 3] = tm / (float)N;
        }
    }
}

// ---------------- launch ---------------------------------------------------------
extern "C" void kernel_launch(void* const* d_in, const int* in_sizes, int n_in,
                              void* d_out, int out_size) {
    const float* V  = (const float*)d_in[0];
    const float* T  = (const float*)d_in[1];
    const float* PV = (const float*)d_in[2];
    const float* PT = (const float*)d_in[3];

    cudaFuncSetAttribute(gemm_mma_kernel, cudaFuncAttributeMaxDynamicSharedMemorySize, SMEM_SIZE);

    zero_cnt_kernel<<<16, 512>>>();
    normalize_kernel<<<N, 128>>>(V, T, PV, PT);
    colstats_kernel<<<dim3(64, 4), 512>>>();
    gemm_mma_kernel<<<dim3(N / (TN * JT), N / TM, 2), NTHR, SMEM_SIZE>>>();
    recheck_kernel<<<1024, 256>>>();
    finalize_kernel<<<1, 512>>>((float*)d_out);
}